// round 1
// baseline (speedup 1.0000x reference)
#include <cuda_runtime.h>
#include <math.h>

#define B_  2
#define N_  2048
#define C_  768
#define H_  12
#define D_  64
#define BH_ 24

// ---------------- scratch (device globals: no runtime allocation) ----------
__device__ float g_q [BH_*N_*D_];
__device__ float g_k [BH_*N_*D_];
__device__ float g_v [BH_*N_*D_];
__device__ float g_o1[BH_*N_*D_];   // stage-1 attention output  [BH,N,D]
__device__ float g_p1[BH_*N_*D_];   // after first projection    [BH,N,D]
__device__ float g_st[BH_*N_*D_];   // normalized sim tokens     [BH,N,D]
__device__ float g_o2[BH_*N_*D_];   // stage-2 attention output  [BH,N,D]

// ---------------------------------------------------------------------------
// GEMM: Y[m,j] = sum_c A[m,c] * W[j,c] + bias[j]
// BM=BN=64, BK=16, 256 threads, 4x4 register tile per thread.
// MODE 0: A = x  [B*N, C] (m = b*N+n), W=[2304,768]  -> scatter into g_q/g_k/g_v
// MODE 1: A = gather(g_o1) as [N*B, C] (m = n*B+b)   -> scatter into g_p1
// MODE 2: A = gather(g_o2) as [N*B, C]               -> store d_out [B,N,C]
// ---------------------------------------------------------------------------
template<int MODE>
__global__ void __launch_bounds__(256) gemm_kernel(
    const float* __restrict__ A, const float* __restrict__ W,
    const float* __restrict__ bias, float* __restrict__ out)
{
    __shared__ float As[16][68];
    __shared__ float Bs[16][68];
    const int bm  = blockIdx.y * 64;
    const int bn  = blockIdx.x * 64;
    const int tid = threadIdx.x;
    const int lr  = tid >> 2;        // 0..63 : row loaded by this thread
    const int lc4 = tid & 3;         // which float4 within 16-wide K slab
    const int tr  = (tid >> 4) * 4;  // compute-tile row base
    const int tc  = (tid & 15) * 4;  // compute-tile col base

    float acc[4][4];
#pragma unroll
    for (int i = 0; i < 4; i++)
#pragma unroll
        for (int j = 0; j < 4; j++) acc[i][j] = 0.f;

    const int m = bm + lr;
    int n_ = 0, b_ = 0;
    if (MODE != 0) { n_ = m / B_; b_ = m % B_; }

    for (int k0 = 0; k0 < C_; k0 += 16) {
        float4 av;
        if (MODE == 0) {
            av = *(const float4*)(A + (size_t)m * C_ + k0 + lc4 * 4);
        } else {
            const float* src = (MODE == 1) ? g_o1 : g_o2;
            int c = k0 + lc4 * 4;
            int h = c >> 6, d = c & 63;
            av = *(const float4*)(src + (((size_t)(b_ * H_ + h)) * N_ + n_) * D_ + d);
        }
        float4 bv = *(const float4*)(W + (size_t)(bn + lr) * C_ + k0 + lc4 * 4);
        As[lc4*4+0][lr] = av.x; As[lc4*4+1][lr] = av.y;
        As[lc4*4+2][lr] = av.z; As[lc4*4+3][lr] = av.w;
        Bs[lc4*4+0][lr] = bv.x; Bs[lc4*4+1][lr] = bv.y;
        Bs[lc4*4+2][lr] = bv.z; Bs[lc4*4+3][lr] = bv.w;
        __syncthreads();
#pragma unroll
        for (int kk = 0; kk < 16; kk++) {
            float a0 = As[kk][tr+0], a1 = As[kk][tr+1], a2 = As[kk][tr+2], a3 = As[kk][tr+3];
            float b0 = Bs[kk][tc+0], b1 = Bs[kk][tc+1], b2 = Bs[kk][tc+2], b3 = Bs[kk][tc+3];
            acc[0][0] += a0*b0; acc[0][1] += a0*b1; acc[0][2] += a0*b2; acc[0][3] += a0*b3;
            acc[1][0] += a1*b0; acc[1][1] += a1*b1; acc[1][2] += a1*b2; acc[1][3] += a1*b3;
            acc[2][0] += a2*b0; acc[2][1] += a2*b1; acc[2][2] += a2*b2; acc[2][3] += a2*b3;
            acc[3][0] += a3*b0; acc[3][1] += a3*b1; acc[3][2] += a3*b2; acc[3][3] += a3*b3;
        }
        __syncthreads();
    }

#pragma unroll
    for (int i = 0; i < 4; i++) {
        int mm = bm + tr + i;
#pragma unroll
        for (int j = 0; j < 4; j++) {
            int jj = bn + tc + j;
            float val = acc[i][j] + bias[jj];
            if (MODE == 0) {
                int part = jj / C_;
                int jq = jj - part * C_;
                int h = jq >> 6, d = jq & 63;
                int bb = mm / N_, nn = mm % N_;
                float* dst = (part == 0) ? g_q : ((part == 1) ? g_k : g_v);
                dst[(((size_t)(bb * H_ + h)) * N_ + nn) * D_ + d] = val;
            } else if (MODE == 1) {
                int h = jj >> 6, d = jj & 63;
                int nn = mm / B_, bb = mm % B_;
                g_p1[(((size_t)(bb * H_ + h)) * N_ + nn) * D_ + d] = val;
            } else {
                int nn = mm / B_, bb = mm % B_;
                out[((size_t)bb * N_ + nn) * C_ + jj] = val;
            }
        }
    }
}

// ---------------------------------------------------------------------------
// Flash attention. BR=64 query rows per block, BC=32 key cols per tile.
// 256 threads: thread t owns row r=t/4, score cols [qtr*8, qtr*8+8),
// output dims [qtr*16, qtr*16+16).
// STAGE 1: Q=g_q, K=g_k, V=g_v, scale=1/8        -> g_o1
// STAGE 2: Q=K=g_st, V=g_v, scale=10, mask s<0   -> g_o2
// ---------------------------------------------------------------------------
template<int STAGE>
__global__ void __launch_bounds__(256) flash_kernel()
{
    __shared__ float sQ[64][68];
    __shared__ float sK[32][68];
    __shared__ float sV[32][68];
    __shared__ float sP[64][33];

    const int tid = threadIdx.x;
    const int r   = tid >> 2;
    const int qtr = tid & 3;
    const int bh  = blockIdx.y;
    const int row0 = blockIdx.x * 64;

    const float* Q = (STAGE == 1) ? g_q : g_st;
    const float* K = (STAGE == 1) ? g_k : g_st;
    const float* V = g_v;
    float*       O = (STAGE == 1) ? g_o1 : g_o2;

    const float* Qb = Q + ((size_t)bh * N_ + row0) * D_;
#pragma unroll
    for (int i = tid; i < 64 * 16; i += 256) {
        int rr = i >> 4, cc = (i & 15) * 4;
        *(float4*)&sQ[rr][cc] = *(const float4*)(Qb + rr * D_ + cc);
    }

    float m_i = -1e30f, l_i = 0.f;
    float acc[16];
#pragma unroll
    for (int d = 0; d < 16; d++) acc[d] = 0.f;

    for (int kt = 0; kt < N_; kt += 32) {
        __syncthreads();   // prior iteration done with sK/sV (also orders sQ load)
        const float* Kb = K + ((size_t)bh * N_ + kt) * D_;
        const float* Vb = V + ((size_t)bh * N_ + kt) * D_;
#pragma unroll
        for (int i = tid; i < 32 * 16; i += 256) {
            int rr = i >> 4, cc = (i & 15) * 4;
            *(float4*)&sK[rr][cc] = *(const float4*)(Kb + rr * D_ + cc);
            *(float4*)&sV[rr][cc] = *(const float4*)(Vb + rr * D_ + cc);
        }
        __syncthreads();

        // scores for my 8 columns
        float s[8];
#pragma unroll
        for (int c = 0; c < 8; c++) s[c] = 0.f;
#pragma unroll
        for (int d = 0; d < 64; d += 4) {
            float4 qv = *(const float4*)&sQ[r][d];
#pragma unroll
            for (int c = 0; c < 8; c++) {
                float4 kv = *(const float4*)&sK[qtr * 8 + c][d];
                s[c] += qv.x * kv.x + qv.y * kv.y + qv.z * kv.z + qv.w * kv.w;
            }
        }
        float tmax = -1e30f;
#pragma unroll
        for (int c = 0; c < 8; c++) {
            if (STAGE == 1) {
                s[c] *= 0.125f;
            } else {
                s[c] *= 10.f;
                if (s[c] < 0.f) s[c] = -1e30f;   // data-dependent mask
            }
            tmax = fmaxf(tmax, s[c]);
        }
        tmax = fmaxf(tmax, __shfl_xor_sync(0xffffffffu, tmax, 1));
        tmax = fmaxf(tmax, __shfl_xor_sync(0xffffffffu, tmax, 2));

        float m_new = fmaxf(m_i, tmax);
        float corr  = __expf(m_i - m_new);
        float psum  = 0.f;
#pragma unroll
        for (int c = 0; c < 8; c++) {
            float p = (s[c] < -1e29f) ? 0.f : __expf(s[c] - m_new);
            sP[r][qtr * 8 + c] = p;
            psum += p;
        }
        psum += __shfl_xor_sync(0xffffffffu, psum, 1);
        psum += __shfl_xor_sync(0xffffffffu, psum, 2);
        l_i = l_i * corr + psum;
        m_i = m_new;
#pragma unroll
        for (int d = 0; d < 16; d++) acc[d] *= corr;
        __syncwarp();   // sP row is produced by 4 adjacent lanes of this warp

#pragma unroll
        for (int c = 0; c < 32; c++) {
            float p = sP[r][c];
#pragma unroll
            for (int d4 = 0; d4 < 4; d4++) {
                float4 vv = *(const float4*)&sV[c][qtr * 16 + d4 * 4];
                acc[d4 * 4 + 0] += p * vv.x;
                acc[d4 * 4 + 1] += p * vv.y;
                acc[d4 * 4 + 2] += p * vv.z;
                acc[d4 * 4 + 3] += p * vv.w;
            }
        }
    }

    float inv_l = 1.f / l_i;
    float* Ob = O + ((size_t)bh * N_ + row0 + r) * D_ + qtr * 16;
#pragma unroll
    for (int d4 = 0; d4 < 4; d4++) {
        float4 o;
        o.x = acc[d4*4+0] * inv_l; o.y = acc[d4*4+1] * inv_l;
        o.z = acc[d4*4+2] * inv_l; o.w = acc[d4*4+3] * inv_l;
        *(float4*)(Ob + d4 * 4) = o;
    }
}

// ---------------------------------------------------------------------------
// Row-normalize g_p1 -> g_st : one warp per (bh, n) row of 64 floats.
// ---------------------------------------------------------------------------
__global__ void __launch_bounds__(256) normalize_kernel()
{
    int warp = (blockIdx.x * blockDim.x + threadIdx.x) >> 5;
    int lane = threadIdx.x & 31;
    if (warp >= BH_ * N_) return;
    float2 v = ((const float2*)(g_p1 + (size_t)warp * D_))[lane];
    float ss = v.x * v.x + v.y * v.y;
#pragma unroll
    for (int o = 16; o; o >>= 1) ss += __shfl_xor_sync(0xffffffffu, ss, o);
    float inv = 1.f / fmaxf(sqrtf(ss), 1e-12f);
    float2 o; o.x = v.x * inv; o.y = v.y * inv;
    ((float2*)(g_st + (size_t)warp * D_))[lane] = o;
}

// ---------------------------------------------------------------------------
extern "C" void kernel_launch(void* const* d_in, const int* in_sizes, int n_in,
                              void* d_out, int out_size)
{
    const float* x      = (const float*)d_in[0];
    const float* qkv_w  = (const float*)d_in[1];
    const float* qkv_b  = (const float*)d_in[2];
    const float* proj_w = (const float*)d_in[3];
    const float* proj_b = (const float*)d_in[4];
    float* out = (float*)d_out;

    // 1) QKV GEMM, scattered into [BH,N,D] head layout
    gemm_kernel<0><<<dim3(36, 64), 256>>>(x, qkv_w, qkv_b, nullptr);
    // 2) stage-1 attention
    flash_kernel<1><<<dim3(N_ / 64, BH_), 256>>>();
    // 3) first projection (gather heads -> [N*B,C] -> scatter back to heads)
    gemm_kernel<1><<<dim3(12, 64), 256>>>(nullptr, proj_w, proj_b, nullptr);
    // 4) L2-normalize token vectors
    normalize_kernel<<<(BH_ * N_ * 32 + 255) / 256, 256>>>();
    // 5) stage-2 self-correlation attention with masking
    flash_kernel<2><<<dim3(N_ / 64, BH_), 256>>>();
    // 6) final projection -> d_out in [B,N,C]
    gemm_kernel<2><<<dim3(12, 64), 256>>>(nullptr, proj_w, proj_b, out);
}

// round 7
// speedup vs baseline: 12.4112x; 12.4112x over previous
#include <cuda_runtime.h>
#include <math.h>
#include <stdint.h>

#define B_  2
#define N_  2048
#define C_  768
#define H_  12
#define D_  64
#define BH_ 24

// ---------------- scratch (device globals) ---------------------------------
__device__ float g_q [BH_*N_*D_];
__device__ float g_k [BH_*N_*D_];
__device__ float g_v [BH_*N_*D_];
__device__ float g_o1[BH_*N_*D_];
__device__ float g_p1[BH_*N_*D_];
__device__ float g_st[BH_*N_*D_];
__device__ float g_o2[BH_*N_*D_];

// ---------------- helpers ---------------------------------------------------
__device__ __forceinline__ uint32_t f2tf(float f) {
    uint32_t r;
    asm("cvt.rna.tf32.f32 %0, %1;" : "=r"(r) : "f"(f));
    return r;
}

// D += A(16x8) * B(8x8), tf32 inputs, f32 accum
__device__ __forceinline__ void mma8(float* d, const uint32_t* a, const uint32_t* b) {
    asm volatile(
        "mma.sync.aligned.m16n8k8.row.col.f32.tf32.tf32.f32 "
        "{%0,%1,%2,%3}, {%4,%5,%6,%7}, {%8,%9}, {%0,%1,%2,%3};"
        : "+f"(d[0]), "+f"(d[1]), "+f"(d[2]), "+f"(d[3])
        : "r"(a[0]), "r"(a[1]), "r"(a[2]), "r"(a[3]), "r"(b[0]), "r"(b[1]));
}

// ---------------------------------------------------------------------------
// tf32 GEMM: Y[m,j] = sum_c A[m,c]*W[j,c] + bias[j].  BM=BN=128, BK=32.
// 8 warps in 2x4 grid, warp tile 64x32 (4 m16-tiles x 4 n8-tiles).
// MODE 0: A=x [B*N,C] (m=b*N+n), W=[2304,768] -> scatter g_q/g_k/g_v
// MODE 1: A=gather(g_o1) [N*B,C] (m=n*B+b)    -> scatter g_p1
// MODE 2: A=gather(g_o2) [N*B,C]              -> d_out [B,N,C]
// ---------------------------------------------------------------------------
template<int MODE>
__global__ void __launch_bounds__(256) gemm_mma(
    const float* __restrict__ Ain, const float* __restrict__ W,
    const float* __restrict__ bias, float* __restrict__ out)
{
    __shared__ uint32_t sA[128 * 36];
    __shared__ uint32_t sW[128 * 36];
    const int tid = threadIdx.x, w = tid >> 5, lane = tid & 31;
    const int g = lane >> 2, tig = lane & 3;
    const int bm = blockIdx.y * 128, bn = blockIdx.x * 128;
    const int wm = (w >> 2) * 64, wn = (w & 3) * 32;

    float acc[4][4][4];
#pragma unroll
    for (int mi = 0; mi < 4; mi++)
#pragma unroll
        for (int nj = 0; nj < 4; nj++)
#pragma unroll
            for (int c = 0; c < 4; c++) acc[mi][nj][c] = 0.f;

    for (int k0 = 0; k0 < C_; k0 += 32) {
        __syncthreads();
#pragma unroll
        for (int i = 0; i < 4; i++) {
            int idx = tid + i * 256;
            int r = idx >> 3, c4 = (idx & 7) * 4;
            float4 v;
            if (MODE == 0) {
                v = *(const float4*)(Ain + (size_t)(bm + r) * C_ + k0 + c4);
            } else {
                const float* src = (MODE == 1) ? g_o1 : g_o2;
                int m = bm + r;
                int nn = m >> 1, bb = m & 1;
                int h = k0 >> 6, dd = (k0 & 63) + c4;
                v = *(const float4*)(src + (((size_t)(bb * H_ + h)) * N_ + nn) * D_ + dd);
            }
            uint4 u;
            u.x = f2tf(v.x); u.y = f2tf(v.y); u.z = f2tf(v.z); u.w = f2tf(v.w);
            *(uint4*)&sA[r * 36 + c4] = u;
            float4 vw = *(const float4*)(W + (size_t)(bn + r) * C_ + k0 + c4);
            uint4 uw;
            uw.x = f2tf(vw.x); uw.y = f2tf(vw.y); uw.z = f2tf(vw.z); uw.w = f2tf(vw.w);
            *(uint4*)&sW[r * 36 + c4] = uw;
        }
        __syncthreads();
#pragma unroll
        for (int ks = 0; ks < 4; ks++) {
            int kk = ks * 8;
            uint32_t af[4][4], bf[4][2];
#pragma unroll
            for (int mi = 0; mi < 4; mi++) {
                int rb = (wm + 16 * mi + g) * 36 + kk + tig;
                af[mi][0] = sA[rb];
                af[mi][1] = sA[rb + 8 * 36];
                af[mi][2] = sA[rb + 4];
                af[mi][3] = sA[rb + 8 * 36 + 4];
            }
#pragma unroll
            for (int nj = 0; nj < 4; nj++) {
                int rb = (wn + 8 * nj + g) * 36 + kk + tig;
                bf[nj][0] = sW[rb];
                bf[nj][1] = sW[rb + 4];
            }
#pragma unroll
            for (int mi = 0; mi < 4; mi++)
#pragma unroll
                for (int nj = 0; nj < 4; nj++)
                    mma8(acc[mi][nj], af[mi], bf[nj]);
        }
    }

    // epilogue: c0/c1 at (row g), c2/c3 at (row g+8); cols 2*tig, 2*tig+1
#pragma unroll
    for (int mi = 0; mi < 4; mi++) {
        int r0 = bm + wm + 16 * mi + g;
        int r1 = r0 + 8;
#pragma unroll
        for (int nj = 0; nj < 4; nj++) {
            int c0 = bn + wn + 8 * nj + 2 * tig;
            float bx = bias[c0], by = bias[c0 + 1];
            float2 v0 = make_float2(acc[mi][nj][0] + bx, acc[mi][nj][1] + by);
            float2 v1 = make_float2(acc[mi][nj][2] + bx, acc[mi][nj][3] + by);
            if (MODE == 0) {
                int part = c0 / C_, jq = c0 - part * C_;
                int h = jq >> 6, d = jq & 63;
                float* base = (part == 0) ? g_q : ((part == 1) ? g_k : g_v);
                int bb0 = r0 >> 11, nn0 = r0 & (N_ - 1);
                int bb1 = r1 >> 11, nn1 = r1 & (N_ - 1);
                *(float2*)(base + (((size_t)(bb0 * H_ + h)) * N_ + nn0) * D_ + d) = v0;
                *(float2*)(base + (((size_t)(bb1 * H_ + h)) * N_ + nn1) * D_ + d) = v1;
            } else if (MODE == 1) {
                int h = c0 >> 6, d = c0 & 63;
                int nn0 = r0 >> 1, bb0 = r0 & 1;
                int nn1 = r1 >> 1, bb1 = r1 & 1;
                *(float2*)(g_p1 + (((size_t)(bb0 * H_ + h)) * N_ + nn0) * D_ + d) = v0;
                *(float2*)(g_p1 + (((size_t)(bb1 * H_ + h)) * N_ + nn1) * D_ + d) = v1;
            } else {
                int nn0 = r0 >> 1, bb0 = r0 & 1;
                int nn1 = r1 >> 1, bb1 = r1 & 1;
                *(float2*)(out + ((size_t)bb0 * N_ + nn0) * C_ + c0) = v0;
                *(float2*)(out + ((size_t)bb1 * N_ + nn1) * C_ + c0) = v1;
            }
        }
    }
}

// ---------------------------------------------------------------------------
// tf32 flash attention, no max-subtraction (scores bounded: stage1 |s|<~4,
// stage2 s<=10). 128 q rows per CTA, 8 warps x 16 rows, 64 keys per iter.
// STAGE 1: Q=g_q K=g_k scale .125 -> g_o1
// STAGE 2: Q=K=g_st scale 10, mask s<0 -> g_o2
// ---------------------------------------------------------------------------
#define FLASH_SMEM ((128*68 + 64*68 + 64*68 + 128*68) * 4)

template<int STAGE>
__global__ void __launch_bounds__(256) flash_mma()
{
    extern __shared__ uint32_t sm[];
    uint32_t* sQ = sm;                 // 128 x 68
    uint32_t* sK = sQ + 128 * 68;      // 64 x 68
    uint32_t* sV = sK + 64 * 68;       // 64 x 68
    uint32_t* sP = sV + 64 * 68;       // 128 x 68

    const int tid = threadIdx.x, w = tid >> 5, lane = tid & 31;
    const int g = lane >> 2, tig = lane & 3;
    const int bh = blockIdx.y, row0 = blockIdx.x * 128;
    const int wm = w * 16;

    const float* Q  = (STAGE == 1) ? g_q : g_st;
    const float* Kp = (STAGE == 1) ? g_k : g_st;
    float*       O  = (STAGE == 1) ? g_o1 : g_o2;

    const float* Qb = Q + ((size_t)bh * N_ + row0) * D_;
#pragma unroll
    for (int i = 0; i < 8; i++) {
        int idx = tid + i * 256;
        int r = idx >> 4, c4 = (idx & 15) * 4;
        float4 v = *(const float4*)(Qb + r * D_ + c4);
        uint4 u;
        u.x = f2tf(v.x); u.y = f2tf(v.y); u.z = f2tf(v.z); u.w = f2tf(v.w);
        *(uint4*)&sQ[r * 68 + c4] = u;
    }

    float oacc[8][4];
#pragma unroll
    for (int nj = 0; nj < 8; nj++)
#pragma unroll
        for (int c = 0; c < 4; c++) oacc[nj][c] = 0.f;
    float rlo = 0.f, rhi = 0.f;

    for (int kt = 0; kt < N_; kt += 64) {
        __syncthreads();   // prev iter done reading sK/sV (also orders sQ once)
        const float* Kb = Kp  + ((size_t)bh * N_ + kt) * D_;
        const float* Vb = g_v + ((size_t)bh * N_ + kt) * D_;
#pragma unroll
        for (int i = 0; i < 4; i++) {
            int idx = tid + i * 256;
            int r = idx >> 4, c4 = (idx & 15) * 4;
            float4 kv = *(const float4*)(Kb + r * D_ + c4);
            uint4 ku;
            ku.x = f2tf(kv.x); ku.y = f2tf(kv.y); ku.z = f2tf(kv.z); ku.w = f2tf(kv.w);
            *(uint4*)&sK[r * 68 + c4] = ku;
            float4 vv = *(const float4*)(Vb + r * D_ + c4);
            uint4 vu;
            vu.x = f2tf(vv.x); vu.y = f2tf(vv.y); vu.z = f2tf(vv.z); vu.w = f2tf(vv.w);
            *(uint4*)&sV[r * 68 + c4] = vu;
        }
        __syncthreads();

        // S = Q K^T  (warp's 16 rows x 64 keys)
        float sacc[8][4];
#pragma unroll
        for (int nj = 0; nj < 8; nj++)
#pragma unroll
            for (int c = 0; c < 4; c++) sacc[nj][c] = 0.f;
#pragma unroll
        for (int ks = 0; ks < 8; ks++) {
            int kk = ks * 8;
            uint32_t af[4];
            int rb = (wm + g) * 68 + kk + tig;
            af[0] = sQ[rb];
            af[1] = sQ[rb + 8 * 68];
            af[2] = sQ[rb + 4];
            af[3] = sQ[rb + 8 * 68 + 4];
#pragma unroll
            for (int nj = 0; nj < 8; nj++) {
                uint32_t bf[2];
                int kb = (8 * nj + g) * 68 + kk + tig;
                bf[0] = sK[kb];
                bf[1] = sK[kb + 4];
                mma8(sacc[nj], af, bf);
            }
        }

        // exp (+ mask), accumulate row sums, store P (tf32) to smem
#pragma unroll
        for (int nj = 0; nj < 8; nj++) {
            float p0, p1, p2, p3;
            if (STAGE == 1) {
                p0 = __expf(sacc[nj][0] * 0.125f);
                p1 = __expf(sacc[nj][1] * 0.125f);
                p2 = __expf(sacc[nj][2] * 0.125f);
                p3 = __expf(sacc[nj][3] * 0.125f);
            } else {
                float s0 = sacc[nj][0] * 10.f, s1 = sacc[nj][1] * 10.f;
                float s2 = sacc[nj][2] * 10.f, s3 = sacc[nj][3] * 10.f;
                p0 = (s0 < 0.f) ? 0.f : __expf(s0);
                p1 = (s1 < 0.f) ? 0.f : __expf(s1);
                p2 = (s2 < 0.f) ? 0.f : __expf(s2);
                p3 = (s3 < 0.f) ? 0.f : __expf(s3);
            }
            rlo += p0 + p1;
            rhi += p2 + p3;
            int pb = (wm + g) * 68 + 8 * nj + 2 * tig;
            uint2 u0; u0.x = f2tf(p0); u0.y = f2tf(p1);
            uint2 u1; u1.x = f2tf(p2); u1.y = f2tf(p3);
            *(uint2*)&sP[pb] = u0;
            *(uint2*)&sP[pb + 8 * 68] = u1;
        }
        __syncwarp();   // P rows are warp-private: warp-level visibility suffices

        // O += P V  (k = 64 keys)
#pragma unroll
        for (int ks = 0; ks < 8; ks++) {
            int kk = ks * 8;
            uint32_t af[4];
            int rb = (wm + g) * 68 + kk + tig;
            af[0] = sP[rb];
            af[1] = sP[rb + 8 * 68];
            af[2] = sP[rb + 4];
            af[3] = sP[rb + 8 * 68 + 4];
#pragma unroll
            for (int nj = 0; nj < 8; nj++) {
                uint32_t bf[2];
                int vb = (kk + tig) * 68 + 8 * nj + g;
                bf[0] = sV[vb];
                bf[1] = sV[vb + 4 * 68];
                mma8(oacc[nj], af, bf);
            }
        }
    }

    // reduce row sums across the 4 lanes of each row group
    rlo += __shfl_xor_sync(0xffffffffu, rlo, 1);
    rlo += __shfl_xor_sync(0xffffffffu, rlo, 2);
    rhi += __shfl_xor_sync(0xffffffffu, rhi, 1);
    rhi += __shfl_xor_sync(0xffffffffu, rhi, 2);
    float ilo = 1.f / rlo, ihi = 1.f / rhi;

    float* Ob = O + ((size_t)bh * N_ + row0 + wm + g) * D_;
#pragma unroll
    for (int nj = 0; nj < 8; nj++) {
        int c0 = 8 * nj + 2 * tig;
        float2 v0 = make_float2(oacc[nj][0] * ilo, oacc[nj][1] * ilo);
        float2 v1 = make_float2(oacc[nj][2] * ihi, oacc[nj][3] * ihi);
        *(float2*)(Ob + c0) = v0;
        *(float2*)(Ob + (size_t)8 * D_ + c0) = v1;
    }
}

// ---------------------------------------------------------------------------
__global__ void __launch_bounds__(256) normalize_kernel()
{
    int warp = (blockIdx.x * blockDim.x + threadIdx.x) >> 5;
    int lane = threadIdx.x & 31;
    if (warp >= BH_ * N_) return;
    float2 v = ((const float2*)(g_p1 + (size_t)warp * D_))[lane];
    float ss = v.x * v.x + v.y * v.y;
#pragma unroll
    for (int o = 16; o; o >>= 1) ss += __shfl_xor_sync(0xffffffffu, ss, o);
    float inv = 1.f / fmaxf(sqrtf(ss), 1e-12f);
    float2 o; o.x = v.x * inv; o.y = v.y * inv;
    ((float2*)(g_st + (size_t)warp * D_))[lane] = o;
}

// ---------------------------------------------------------------------------
extern "C" void kernel_launch(void* const* d_in, const int* in_sizes, int n_in,
                              void* d_out, int out_size)
{
    const float* x      = (const float*)d_in[0];
    const float* qkv_w  = (const float*)d_in[1];
    const float* qkv_b  = (const float*)d_in[2];
    const float* proj_w = (const float*)d_in[3];
    const float* proj_b = (const float*)d_in[4];
    float* out = (float*)d_out;

    cudaFuncSetAttribute(flash_mma<1>, cudaFuncAttributeMaxDynamicSharedMemorySize, FLASH_SMEM);
    cudaFuncSetAttribute(flash_mma<2>, cudaFuncAttributeMaxDynamicSharedMemorySize, FLASH_SMEM);

    // 1) QKV GEMM -> g_q/g_k/g_v (head layout)
    gemm_mma<0><<<dim3(18, 32), 256>>>(x, qkv_w, qkv_b, nullptr);
    // 2) stage-1 attention
    flash_mma<1><<<dim3(N_ / 128, BH_), 256, FLASH_SMEM>>>();
    // 3) first projection -> g_p1 (head layout)
    gemm_mma<1><<<dim3(6, 32), 256>>>(nullptr, proj_w, proj_b, nullptr);
    // 4) L2-normalize
    normalize_kernel<<<(BH_ * N_ * 32 + 255) / 256, 256>>>();
    // 5) stage-2 self-correlation attention
    flash_mma<2><<<dim3(N_ / 128, BH_), 256, FLASH_SMEM>>>();
    // 6) final projection -> d_out
    gemm_mma<2><<<dim3(6, 32), 256>>>(nullptr, proj_w, proj_b, out);
}

// round 9
// speedup vs baseline: 12.4333x; 1.0018x over previous
#include <cuda_runtime.h>
#include <math.h>
#include <stdint.h>

#define B_  2
#define N_  2048
#define C_  768
#define H_  12
#define D_  64
#define BH_ 24

// ---------------- scratch (device globals) ---------------------------------
__device__ float g_q [BH_*N_*D_];
__device__ float g_k [BH_*N_*D_];
__device__ float g_v [BH_*N_*D_];
__device__ float g_o1[BH_*N_*D_];
__device__ float g_p1[BH_*N_*D_];
__device__ float g_st[BH_*N_*D_];
__device__ float g_o2[BH_*N_*D_];

// ---------------- helpers ---------------------------------------------------
__device__ __forceinline__ uint32_t f2tf(float f) {
    uint32_t r;
    asm("cvt.rna.tf32.f32 %0, %1;" : "=r"(r) : "f"(f));
    return r;
}

// D += A(16x8) * B(8x8), tf32 inputs, f32 accum
__device__ __forceinline__ void mma8(float* d, const uint32_t* a, const uint32_t* b) {
    asm volatile(
        "mma.sync.aligned.m16n8k8.row.col.f32.tf32.tf32.f32 "
        "{%0,%1,%2,%3}, {%4,%5,%6,%7}, {%8,%9}, {%0,%1,%2,%3};"
        : "+f"(d[0]), "+f"(d[1]), "+f"(d[2]), "+f"(d[3])
        : "r"(a[0]), "r"(a[1]), "r"(a[2]), "r"(a[3]), "r"(b[0]), "r"(b[1]));
}

__device__ __forceinline__ uint4 cvt4(float4 v) {
    uint4 u;
    u.x = f2tf(v.x); u.y = f2tf(v.y); u.z = f2tf(v.z); u.w = f2tf(v.w);
    return u;
}

// ---------------------------------------------------------------------------
// tf32 GEMM: Y[m,j] = sum_c A[m,c]*W[j,c] + bias[j].  BM=BN=128, BK=32.
// 8 warps in 2x4 grid, warp tile 64x32.  Software-pipelined: LDG(k+1) at top
// of compute (latency hidden), cvt+STS after bottom barrier.
// MODE 0: A=x [B*N,C], W=[2304,768] -> scatter g_q/g_k/g_v
// MODE 1: A=gather(g_o1) [N*B,C]    -> scatter g_p1
// MODE 2: A=gather(g_o2) [N*B,C]    -> d_out [B,N,C]
// ---------------------------------------------------------------------------
template<int MODE>
__global__ void __launch_bounds__(256) gemm_mma(
    const float* __restrict__ Ain, const float* __restrict__ W,
    const float* __restrict__ bias, float* __restrict__ out)
{
    __shared__ uint32_t sA[128 * 36];
    __shared__ uint32_t sW[128 * 36];
    const int tid = threadIdx.x, w = tid >> 5, lane = tid & 31;
    const int g = lane >> 2, tig = lane & 3;
    const int bm = blockIdx.y * 128, bn = blockIdx.x * 128;
    const int wm = (w >> 2) * 64, wn = (w & 3) * 32;
    const int pr = tid >> 3;          // staging row (2 rows per thread: pr, pr+... )
    const int pc = (tid & 7) * 4;     // staging col (float4)

    float acc[4][4][4];
#pragma unroll
    for (int mi = 0; mi < 4; mi++)
#pragma unroll
        for (int nj = 0; nj < 4; nj++)
#pragma unroll
            for (int c = 0; c < 4; c++) acc[mi][nj][c] = 0.f;

    float4 areg[4], wreg[4];

    // prefetch k-chunk 0
#pragma unroll
    for (int i = 0; i < 4; i++) {
        int r = pr + i * 32;
        if (MODE == 0) {
            areg[i] = *(const float4*)(Ain + (size_t)(bm + r) * C_ + pc);
        } else {
            const float* src = (MODE == 1) ? g_o1 : g_o2;
            int m = bm + r, nn = m >> 1, bb = m & 1;
            areg[i] = *(const float4*)(src + ((size_t)(bb * H_) * N_ + nn) * D_ + pc);
        }
        wreg[i] = *(const float4*)(W + (size_t)(bn + r) * C_ + pc);
    }
#pragma unroll
    for (int i = 0; i < 4; i++) {
        int r = pr + i * 32;
        *(uint4*)&sA[r * 36 + pc] = cvt4(areg[i]);
        *(uint4*)&sW[r * 36 + pc] = cvt4(wreg[i]);
    }

    for (int k0 = 0; k0 < C_; k0 += 32) {
        __syncthreads();
        const bool more = (k0 + 32 < C_);
        if (more) {
            int kn = k0 + 32;
#pragma unroll
            for (int i = 0; i < 4; i++) {
                int r = pr + i * 32;
                if (MODE == 0) {
                    areg[i] = *(const float4*)(Ain + (size_t)(bm + r) * C_ + kn + pc);
                } else {
                    const float* src = (MODE == 1) ? g_o1 : g_o2;
                    int m = bm + r, nn = m >> 1, bb = m & 1;
                    int h = kn >> 6, dd = (kn & 63) + pc;
                    areg[i] = *(const float4*)(src + (((size_t)(bb * H_ + h)) * N_ + nn) * D_ + dd);
                }
                wreg[i] = *(const float4*)(W + (size_t)(bn + r) * C_ + kn + pc);
            }
        }
#pragma unroll
        for (int ks = 0; ks < 4; ks++) {
            int kk = ks * 8;
            uint32_t af[4][4], bf[4][2];
#pragma unroll
            for (int mi = 0; mi < 4; mi++) {
                int rb = (wm + 16 * mi + g) * 36 + kk + tig;
                af[mi][0] = sA[rb];
                af[mi][1] = sA[rb + 8 * 36];
                af[mi][2] = sA[rb + 4];
                af[mi][3] = sA[rb + 8 * 36 + 4];
            }
#pragma unroll
            for (int nj = 0; nj < 4; nj++) {
                int rb = (wn + 8 * nj + g) * 36 + kk + tig;
                bf[nj][0] = sW[rb];
                bf[nj][1] = sW[rb + 4];
            }
#pragma unroll
            for (int mi = 0; mi < 4; mi++)
#pragma unroll
                for (int nj = 0; nj < 4; nj++)
                    mma8(acc[mi][nj], af[mi], bf[nj]);
        }
        __syncthreads();
        if (more) {
#pragma unroll
            for (int i = 0; i < 4; i++) {
                int r = pr + i * 32;
                *(uint4*)&sA[r * 36 + pc] = cvt4(areg[i]);
                *(uint4*)&sW[r * 36 + pc] = cvt4(wreg[i]);
            }
        }
    }

    // epilogue: c0/c1 at (row g), c2/c3 at (row g+8); cols 2*tig, 2*tig+1
#pragma unroll
    for (int mi = 0; mi < 4; mi++) {
        int r0 = bm + wm + 16 * mi + g;
        int r1 = r0 + 8;
#pragma unroll
        for (int nj = 0; nj < 4; nj++) {
            int c0 = bn + wn + 8 * nj + 2 * tig;
            float bx = bias[c0], by = bias[c0 + 1];
            float2 v0 = make_float2(acc[mi][nj][0] + bx, acc[mi][nj][1] + by);
            float2 v1 = make_float2(acc[mi][nj][2] + bx, acc[mi][nj][3] + by);
            if (MODE == 0) {
                int part = c0 / C_, jq = c0 - part * C_;
                int h = jq >> 6, d = jq & 63;
                float* base = (part == 0) ? g_q : ((part == 1) ? g_k : g_v);
                int bb0 = r0 >> 11, nn0 = r0 & (N_ - 1);
                int bb1 = r1 >> 11, nn1 = r1 & (N_ - 1);
                *(float2*)(base + (((size_t)(bb0 * H_ + h)) * N_ + nn0) * D_ + d) = v0;
                *(float2*)(base + (((size_t)(bb1 * H_ + h)) * N_ + nn1) * D_ + d) = v1;
            } else if (MODE == 1) {
                int h = c0 >> 6, d = c0 & 63;
                int nn0 = r0 >> 1, bb0 = r0 & 1;
                int nn1 = r1 >> 1, bb1 = r1 & 1;
                *(float2*)(g_p1 + (((size_t)(bb0 * H_ + h)) * N_ + nn0) * D_ + d) = v0;
                *(float2*)(g_p1 + (((size_t)(bb1 * H_ + h)) * N_ + nn1) * D_ + d) = v1;
            } else {
                int nn0 = r0 >> 1, bb0 = r0 & 1;
                int nn1 = r1 >> 1, bb1 = r1 & 1;
                *(float2*)(out + ((size_t)bb0 * N_ + nn0) * C_ + c0) = v0;
                *(float2*)(out + ((size_t)bb1 * N_ + nn1) * C_ + c0) = v1;
            }
        }
    }
}

// ---------------------------------------------------------------------------
// tf32 flash attention, no max-subtraction (scores bounded).  128 q rows per
// CTA, 8 warps x 16 rows, 64 keys per iter.  Software-pipelined K/V prefetch:
// LDG K(i+1) hidden behind S-mma, LDG V(i+1) behind exp+O-mma; cvt+STS after
// the bottom barrier into the single buffer.
// STAGE 1: Q=g_q K=g_k scale .125 -> g_o1
// STAGE 2: Q=K=g_st scale 10, mask s<0 -> g_o2
// ---------------------------------------------------------------------------
#define FLASH_SMEM ((128*68 + 64*68 + 64*68 + 128*68) * 4)

template<int STAGE>
__global__ void __launch_bounds__(256) flash_mma()
{
    extern __shared__ uint32_t sm[];
    uint32_t* sQ = sm;                 // 128 x 68
    uint32_t* sK = sQ + 128 * 68;      // 64 x 68
    uint32_t* sV = sK + 64 * 68;       // 64 x 68
    uint32_t* sP = sV + 64 * 68;       // 128 x 68

    const int tid = threadIdx.x, w = tid >> 5, lane = tid & 31;
    const int g = lane >> 2, tig = lane & 3;
    const int bh = blockIdx.y, row0 = blockIdx.x * 128;
    const int wm = w * 16;
    const int pr = tid >> 4;          // staging row base (K/V: rows pr, pr+16, ...)
    const int pc = (tid & 15) * 4;    // staging col

    const float* Q  = (STAGE == 1) ? g_q : g_st;
    const float* Kp = (STAGE == 1) ? g_k : g_st;
    float*       O  = (STAGE == 1) ? g_o1 : g_o2;

    const float* Qb = Q + ((size_t)bh * N_ + row0) * D_;
#pragma unroll
    for (int i = 0; i < 8; i++) {
        int idx = tid + i * 256;
        int r = idx >> 4, c4 = (idx & 15) * 4;
        *(uint4*)&sQ[r * 68 + c4] = cvt4(*(const float4*)(Qb + r * D_ + c4));
    }

    const float* KbB = Kp  + (size_t)bh * N_ * D_;
    const float* VbB = g_v + (size_t)bh * N_ * D_;

    float4 kreg[4], vreg[4];
#pragma unroll
    for (int i = 0; i < 4; i++) {
        int r = pr + i * 16;
        kreg[i] = *(const float4*)(KbB + (size_t)r * D_ + pc);
        vreg[i] = *(const float4*)(VbB + (size_t)r * D_ + pc);
    }
#pragma unroll
    for (int i = 0; i < 4; i++) {
        int r = pr + i * 16;
        *(uint4*)&sK[r * 68 + pc] = cvt4(kreg[i]);
        *(uint4*)&sV[r * 68 + pc] = cvt4(vreg[i]);
    }

    float oacc[8][4];
#pragma unroll
    for (int nj = 0; nj < 8; nj++)
#pragma unroll
        for (int c = 0; c < 4; c++) oacc[nj][c] = 0.f;
    float rlo = 0.f, rhi = 0.f;

    for (int kt = 0; kt < N_; kt += 64) {
        __syncthreads();   // staged tile visible (also covers sQ on iter 0)
        const bool more = (kt + 64 < N_);

        // prefetch K(i+1): latency hidden behind S-mma
        if (more) {
            const float* Kb = KbB + (size_t)(kt + 64) * D_;
#pragma unroll
            for (int i = 0; i < 4; i++)
                kreg[i] = *(const float4*)(Kb + (size_t)(pr + i * 16) * D_ + pc);
        }

        // S = Q K^T  (warp's 16 rows x 64 keys)
        float sacc[8][4];
#pragma unroll
        for (int nj = 0; nj < 8; nj++)
#pragma unroll
            for (int c = 0; c < 4; c++) sacc[nj][c] = 0.f;
#pragma unroll
        for (int ks = 0; ks < 8; ks++) {
            int kk = ks * 8;
            uint32_t af[4];
            int rb = (wm + g) * 68 + kk + tig;
            af[0] = sQ[rb];
            af[1] = sQ[rb + 8 * 68];
            af[2] = sQ[rb + 4];
            af[3] = sQ[rb + 8 * 68 + 4];
#pragma unroll
            for (int nj = 0; nj < 8; nj++) {
                uint32_t bf[2];
                int kb = (8 * nj + g) * 68 + kk + tig;
                bf[0] = sK[kb];
                bf[1] = sK[kb + 4];
                mma8(sacc[nj], af, bf);
            }
        }

        // prefetch V(i+1): latency hidden behind exp + O-mma
        if (more) {
            const float* Vb = VbB + (size_t)(kt + 64) * D_;
#pragma unroll
            for (int i = 0; i < 4; i++)
                vreg[i] = *(const float4*)(Vb + (size_t)(pr + i * 16) * D_ + pc);
        }

        // exp (+ mask), row sums, store P (tf32) to smem
#pragma unroll
        for (int nj = 0; nj < 8; nj++) {
            float p0, p1, p2, p3;
            if (STAGE == 1) {
                p0 = __expf(sacc[nj][0] * 0.125f);
                p1 = __expf(sacc[nj][1] * 0.125f);
                p2 = __expf(sacc[nj][2] * 0.125f);
                p3 = __expf(sacc[nj][3] * 0.125f);
            } else {
                float s0 = sacc[nj][0] * 10.f, s1 = sacc[nj][1] * 10.f;
                float s2 = sacc[nj][2] * 10.f, s3 = sacc[nj][3] * 10.f;
                p0 = (s0 < 0.f) ? 0.f : __expf(s0);
                p1 = (s1 < 0.f) ? 0.f : __expf(s1);
                p2 = (s2 < 0.f) ? 0.f : __expf(s2);
                p3 = (s3 < 0.f) ? 0.f : __expf(s3);
            }
            rlo += p0 + p1;
            rhi += p2 + p3;
            int pb = (wm + g) * 68 + 8 * nj + 2 * tig;
            uint2 u0; u0.x = f2tf(p0); u0.y = f2tf(p1);
            uint2 u1; u1.x = f2tf(p2); u1.y = f2tf(p3);
            *(uint2*)&sP[pb] = u0;
            *(uint2*)&sP[pb + 8 * 68] = u1;
        }
        __syncwarp();   // P rows are warp-private

        // O += P V
#pragma unroll
        for (int ks = 0; ks < 8; ks++) {
            int kk = ks * 8;
            uint32_t af[4];
            int rb = (wm + g) * 68 + kk + tig;
            af[0] = sP[rb];
            af[1] = sP[rb + 8 * 68];
            af[2] = sP[rb + 4];
            af[3] = sP[rb + 8 * 68 + 4];
#pragma unroll
            for (int nj = 0; nj < 8; nj++) {
                uint32_t bf[2];
                int vb = (kk + tig) * 68 + 8 * nj + g;
                bf[0] = sV[vb];
                bf[1] = sV[vb + 4 * 68];
                mma8(oacc[nj], af, bf);
            }
        }

        __syncthreads();   // all reads of sK/sV done
        if (more) {
#pragma unroll
            for (int i = 0; i < 4; i++) {
                int r = pr + i * 16;
                *(uint4*)&sK[r * 68 + pc] = cvt4(kreg[i]);
                *(uint4*)&sV[r * 68 + pc] = cvt4(vreg[i]);
            }
        }
    }

    rlo += __shfl_xor_sync(0xffffffffu, rlo, 1);
    rlo += __shfl_xor_sync(0xffffffffu, rlo, 2);
    rhi += __shfl_xor_sync(0xffffffffu, rhi, 1);
    rhi += __shfl_xor_sync(0xffffffffu, rhi, 2);
    float ilo = 1.f / rlo, ihi = 1.f / rhi;

    float* Ob = O + ((size_t)bh * N_ + row0 + wm + g) * D_;
#pragma unroll
    for (int nj = 0; nj < 8; nj++) {
        int c0 = 8 * nj + 2 * tig;
        float2 v0 = make_float2(oacc[nj][0] * ilo, oacc[nj][1] * ilo);
        float2 v1 = make_float2(oacc[nj][2] * ihi, oacc[nj][3] * ihi);
        *(float2*)(Ob + c0) = v0;
        *(float2*)(Ob + (size_t)8 * D_ + c0) = v1;
    }
}

// ---------------------------------------------------------------------------
__global__ void __launch_bounds__(256) normalize_kernel()
{
    int warp = (blockIdx.x * blockDim.x + threadIdx.x) >> 5;
    int lane = threadIdx.x & 31;
    if (warp >= BH_ * N_) return;
    float2 v = ((const float2*)(g_p1 + (size_t)warp * D_))[lane];
    float ss = v.x * v.x + v.y * v.y;
#pragma unroll
    for (int o = 16; o; o >>= 1) ss += __shfl_xor_sync(0xffffffffu, ss, o);
    float inv = 1.f / fmaxf(sqrtf(ss), 1e-12f);
    float2 o; o.x = v.x * inv; o.y = v.y * inv;
    ((float2*)(g_st + (size_t)warp * D_))[lane] = o;
}

// ---------------------------------------------------------------------------
extern "C" void kernel_launch(void* const* d_in, const int* in_sizes, int n_in,
                              void* d_out, int out_size)
{
    const float* x      = (const float*)d_in[0];
    const float* qkv_w  = (const float*)d_in[1];
    const float* qkv_b  = (const float*)d_in[2];
    const float* proj_w = (const float*)d_in[3];
    const float* proj_b = (const float*)d_in[4];
    float* out = (float*)d_out;

    cudaFuncSetAttribute(flash_mma<1>, cudaFuncAttributeMaxDynamicSharedMemorySize, FLASH_SMEM);
    cudaFuncSetAttribute(flash_mma<2>, cudaFuncAttributeMaxDynamicSharedMemorySize, FLASH_SMEM);

    // 1) QKV GEMM -> g_q/g_k/g_v (head layout)
    gemm_mma<0><<<dim3(18, 32), 256>>>(x, qkv_w, qkv_b, nullptr);
    // 2) stage-1 attention
    flash_mma<1><<<dim3(N_ / 128, BH_), 256, FLASH_SMEM>>>();
    // 3) first projection -> g_p1 (head layout)
    gemm_mma<1><<<dim3(6, 32), 256>>>(nullptr, proj_w, proj_b, nullptr);
    // 4) L2-normalize
    normalize_kernel<<<(BH_ * N_ * 32 + 255) / 256, 256>>>();
    // 5) stage-2 self-correlation attention
    flash_mma<2><<<dim3(N_ / 128, BH_), 256, FLASH_SMEM>>>();
    // 6) final projection -> d_out
    gemm_mma<2><<<dim3(6, 32), 256>>>(nullptr, proj_w, proj_b, out);
}

// round 10
// speedup vs baseline: 15.7176x; 1.2642x over previous
#include <cuda_runtime.h>
#include <math.h>
#include <stdint.h>

#define B_  2
#define N_  2048
#define C_  768
#define H_  12
#define D_  64
#define BH_ 24

// ---------------- scratch (device globals) ---------------------------------
__device__ float g_q [BH_*N_*D_];
__device__ float g_k [BH_*N_*D_];
__device__ float g_v [BH_*N_*D_];
__device__ float g_o1[BH_*N_*D_];
__device__ float g_p1[BH_*N_*D_];
__device__ float g_st[BH_*N_*D_];
__device__ float g_o2[BH_*N_*D_];

// ---------------- helpers ---------------------------------------------------
__device__ __forceinline__ uint32_t f2tf(float f) {
    uint32_t r;
    asm("cvt.rna.tf32.f32 %0, %1;" : "=r"(r) : "f"(f));
    return r;
}
__device__ __forceinline__ float ex2a(float x) {
    float r;
    asm("ex2.approx.f32 %0, %1;" : "=f"(r) : "f"(x));
    return r;
}

// D += A(16x8) * B(8x8), tf32 inputs, f32 accum
__device__ __forceinline__ void mma8(float* d, const uint32_t* a, const uint32_t* b) {
    asm volatile(
        "mma.sync.aligned.m16n8k8.row.col.f32.tf32.tf32.f32 "
        "{%0,%1,%2,%3}, {%4,%5,%6,%7}, {%8,%9}, {%0,%1,%2,%3};"
        : "+f"(d[0]), "+f"(d[1]), "+f"(d[2]), "+f"(d[3])
        : "r"(a[0]), "r"(a[1]), "r"(a[2]), "r"(a[3]), "r"(b[0]), "r"(b[1]));
}

__device__ __forceinline__ uint4 cvt4(float4 v) {
    uint4 u;
    u.x = f2tf(v.x); u.y = f2tf(v.y); u.z = f2tf(v.z); u.w = f2tf(v.w);
    return u;
}

// ---------------------------------------------------------------------------
// tf32 GEMM (unchanged from R9): BM=BN=128, BK=32, 8 warps 2x4, warp 64x32.
// MODE 0: A=x [B*N,C], W=[2304,768] -> scatter g_q/g_k/g_v
// MODE 1: A=gather(g_o1) [N*B,C]    -> scatter g_p1
// MODE 2: A=gather(g_o2) [N*B,C]    -> d_out [B,N,C]
// ---------------------------------------------------------------------------
template<int MODE>
__global__ void __launch_bounds__(256) gemm_mma(
    const float* __restrict__ Ain, const float* __restrict__ W,
    const float* __restrict__ bias, float* __restrict__ out)
{
    __shared__ uint32_t sA[128 * 36];
    __shared__ uint32_t sW[128 * 36];
    const int tid = threadIdx.x, w = tid >> 5, lane = tid & 31;
    const int g = lane >> 2, tig = lane & 3;
    const int bm = blockIdx.y * 128, bn = blockIdx.x * 128;
    const int wm = (w >> 2) * 64, wn = (w & 3) * 32;
    const int pr = tid >> 3;
    const int pc = (tid & 7) * 4;

    float acc[4][4][4];
#pragma unroll
    for (int mi = 0; mi < 4; mi++)
#pragma unroll
        for (int nj = 0; nj < 4; nj++)
#pragma unroll
            for (int c = 0; c < 4; c++) acc[mi][nj][c] = 0.f;

    float4 areg[4], wreg[4];

#pragma unroll
    for (int i = 0; i < 4; i++) {
        int r = pr + i * 32;
        if (MODE == 0) {
            areg[i] = *(const float4*)(Ain + (size_t)(bm + r) * C_ + pc);
        } else {
            const float* src = (MODE == 1) ? g_o1 : g_o2;
            int m = bm + r, nn = m >> 1, bb = m & 1;
            areg[i] = *(const float4*)(src + ((size_t)(bb * H_) * N_ + nn) * D_ + pc);
        }
        wreg[i] = *(const float4*)(W + (size_t)(bn + r) * C_ + pc);
    }
#pragma unroll
    for (int i = 0; i < 4; i++) {
        int r = pr + i * 32;
        *(uint4*)&sA[r * 36 + pc] = cvt4(areg[i]);
        *(uint4*)&sW[r * 36 + pc] = cvt4(wreg[i]);
    }

    for (int k0 = 0; k0 < C_; k0 += 32) {
        __syncthreads();
        const bool more = (k0 + 32 < C_);
        if (more) {
            int kn = k0 + 32;
#pragma unroll
            for (int i = 0; i < 4; i++) {
                int r = pr + i * 32;
                if (MODE == 0) {
                    areg[i] = *(const float4*)(Ain + (size_t)(bm + r) * C_ + kn + pc);
                } else {
                    const float* src = (MODE == 1) ? g_o1 : g_o2;
                    int m = bm + r, nn = m >> 1, bb = m & 1;
                    int h = kn >> 6, dd = (kn & 63) + pc;
                    areg[i] = *(const float4*)(src + (((size_t)(bb * H_ + h)) * N_ + nn) * D_ + dd);
                }
                wreg[i] = *(const float4*)(W + (size_t)(bn + r) * C_ + kn + pc);
            }
        }
#pragma unroll
        for (int ks = 0; ks < 4; ks++) {
            int kk = ks * 8;
            uint32_t af[4][4], bf[4][2];
#pragma unroll
            for (int mi = 0; mi < 4; mi++) {
                int rb = (wm + 16 * mi + g) * 36 + kk + tig;
                af[mi][0] = sA[rb];
                af[mi][1] = sA[rb + 8 * 36];
                af[mi][2] = sA[rb + 4];
                af[mi][3] = sA[rb + 8 * 36 + 4];
            }
#pragma unroll
            for (int nj = 0; nj < 4; nj++) {
                int rb = (wn + 8 * nj + g) * 36 + kk + tig;
                bf[nj][0] = sW[rb];
                bf[nj][1] = sW[rb + 4];
            }
#pragma unroll
            for (int mi = 0; mi < 4; mi++)
#pragma unroll
                for (int nj = 0; nj < 4; nj++)
                    mma8(acc[mi][nj], af[mi], bf[nj]);
        }
        __syncthreads();
        if (more) {
#pragma unroll
            for (int i = 0; i < 4; i++) {
                int r = pr + i * 32;
                *(uint4*)&sA[r * 36 + pc] = cvt4(areg[i]);
                *(uint4*)&sW[r * 36 + pc] = cvt4(wreg[i]);
            }
        }
    }

#pragma unroll
    for (int mi = 0; mi < 4; mi++) {
        int r0 = bm + wm + 16 * mi + g;
        int r1 = r0 + 8;
#pragma unroll
        for (int nj = 0; nj < 4; nj++) {
            int c0 = bn + wn + 8 * nj + 2 * tig;
            float bx = bias[c0], by = bias[c0 + 1];
            float2 v0 = make_float2(acc[mi][nj][0] + bx, acc[mi][nj][1] + by);
            float2 v1 = make_float2(acc[mi][nj][2] + bx, acc[mi][nj][3] + by);
            if (MODE == 0) {
                int part = c0 / C_, jq = c0 - part * C_;
                int h = jq >> 6, d = jq & 63;
                float* base = (part == 0) ? g_q : ((part == 1) ? g_k : g_v);
                int bb0 = r0 >> 11, nn0 = r0 & (N_ - 1);
                int bb1 = r1 >> 11, nn1 = r1 & (N_ - 1);
                *(float2*)(base + (((size_t)(bb0 * H_ + h)) * N_ + nn0) * D_ + d) = v0;
                *(float2*)(base + (((size_t)(bb1 * H_ + h)) * N_ + nn1) * D_ + d) = v1;
            } else if (MODE == 1) {
                int h = c0 >> 6, d = c0 & 63;
                int nn0 = r0 >> 1, bb0 = r0 & 1;
                int nn1 = r1 >> 1, bb1 = r1 & 1;
                *(float2*)(g_p1 + (((size_t)(bb0 * H_ + h)) * N_ + nn0) * D_ + d) = v0;
                *(float2*)(g_p1 + (((size_t)(bb1 * H_ + h)) * N_ + nn1) * D_ + d) = v1;
            } else {
                int nn0 = r0 >> 1, bb0 = r0 & 1;
                int nn1 = r1 >> 1, bb1 = r1 & 1;
                *(float2*)(out + ((size_t)bb0 * N_ + nn0) * C_ + c0) = v0;
                *(float2*)(out + ((size_t)bb1 * N_ + nn1) * C_ + c0) = v1;
            }
        }
    }
}

// ---------------------------------------------------------------------------
// tf32 flash attention. 128 q rows/CTA, 8 warps x 16 rows, 64 keys/iter.
// No sP: accumulator->A-fragment relayout via shfl. sV stride 72 (conflict-
// free transposed fragment loads). 2 CTAs/SM (70.6KB smem, <=128 regs).
// STAGE 1: Q=g_q K=g_k scale .125 -> g_o1
// STAGE 2: Q=K=g_st scale 10, mask s<0 -> g_o2
// ---------------------------------------------------------------------------
#define FLASH_SMEM ((128*68 + 64*68 + 64*72) * 4)

template<int STAGE>
__global__ void __launch_bounds__(256, 2) flash_mma()
{
    extern __shared__ uint32_t sm[];
    uint32_t* sQ = sm;                 // 128 x 68
    uint32_t* sK = sQ + 128 * 68;      // 64 x 68
    uint32_t* sV = sK + 64 * 68;       // 64 x 72 (transposed-access stride)

    const int tid = threadIdx.x, w = tid >> 5, lane = tid & 31;
    const int g = lane >> 2, tig = lane & 3;
    const int bh = blockIdx.y, row0 = blockIdx.x * 128;
    const int wm = w * 16;
    const int pr = tid >> 4;          // staging row base
    const int pc = (tid & 15) * 4;    // staging col

    const float* Q  = (STAGE == 1) ? g_q : g_st;
    const float* Kp = (STAGE == 1) ? g_k : g_st;
    float*       O  = (STAGE == 1) ? g_o1 : g_o2;

    const float* Qb = Q + ((size_t)bh * N_ + row0) * D_;
#pragma unroll
    for (int i = 0; i < 8; i++) {
        int idx = tid + i * 256;
        int r = idx >> 4, c4 = (idx & 15) * 4;
        *(uint4*)&sQ[r * 68 + c4] = cvt4(*(const float4*)(Qb + r * D_ + c4));
    }

    const float* KbB = Kp  + (size_t)bh * N_ * D_;
    const float* VbB = g_v + (size_t)bh * N_ * D_;

    float oacc[8][4];
#pragma unroll
    for (int nj = 0; nj < 8; nj++)
#pragma unroll
        for (int c = 0; c < 4; c++) oacc[nj][c] = 0.f;
    float rlo = 0.f, rhi = 0.f;

    const int src0 = (lane & ~3) | (tig >> 1);
    const int src1 = src0 + 2;
    const bool hi = tig & 1;

    for (int kt = 0; kt < N_; kt += 64) {
        // gmem loads issued before the barrier: latency overlaps barrier drain
        float4 kv[4], vv[4];
#pragma unroll
        for (int i = 0; i < 4; i++) {
            int r = kt + pr + i * 16;
            kv[i] = *(const float4*)(KbB + (size_t)r * D_ + pc);
            vv[i] = *(const float4*)(VbB + (size_t)r * D_ + pc);
        }
        __syncthreads();   // prior iteration's readers done (iter0: trivial)
#pragma unroll
        for (int i = 0; i < 4; i++) {
            int r = pr + i * 16;
            *(uint4*)&sK[r * 68 + pc] = cvt4(kv[i]);
            *(uint4*)&sV[r * 72 + pc] = cvt4(vv[i]);
        }
        __syncthreads();   // staged tile visible (also covers sQ on iter 0)

        // S = Q K^T  (warp's 16 rows x 64 keys)
        float sacc[8][4];
#pragma unroll
        for (int nj = 0; nj < 8; nj++)
#pragma unroll
            for (int c = 0; c < 4; c++) sacc[nj][c] = 0.f;
#pragma unroll
        for (int ks = 0; ks < 8; ks++) {
            int kk = ks * 8;
            uint32_t af[4];
            int rb = (wm + g) * 68 + kk + tig;
            af[0] = sQ[rb];
            af[1] = sQ[rb + 8 * 68];
            af[2] = sQ[rb + 4];
            af[3] = sQ[rb + 8 * 68 + 4];
#pragma unroll
            for (int nj = 0; nj < 8; nj++) {
                uint32_t bf[2];
                int kb = (8 * nj + g) * 68 + kk + tig;
                bf[0] = sK[kb];
                bf[1] = sK[kb + 4];
                mma8(sacc[nj], af, bf);
            }
        }

        // softmax numerator in-place (scores bounded; no max subtraction)
#pragma unroll
        for (int nj = 0; nj < 8; nj++) {
            if (STAGE == 1) {
                // exp(0.125*s) = 2^(s * 0.125*log2e)
                sacc[nj][0] = ex2a(sacc[nj][0] * 0.18033688011112042f);
                sacc[nj][1] = ex2a(sacc[nj][1] * 0.18033688011112042f);
                sacc[nj][2] = ex2a(sacc[nj][2] * 0.18033688011112042f);
                sacc[nj][3] = ex2a(sacc[nj][3] * 0.18033688011112042f);
            } else {
                // exp(10*s) masked at s<0 ; 2^(s * 10*log2e)
                float s0 = sacc[nj][0], s1 = sacc[nj][1];
                float s2 = sacc[nj][2], s3 = sacc[nj][3];
                sacc[nj][0] = (s0 < 0.f) ? 0.f : ex2a(s0 * 14.426950408889634f);
                sacc[nj][1] = (s1 < 0.f) ? 0.f : ex2a(s1 * 14.426950408889634f);
                sacc[nj][2] = (s2 < 0.f) ? 0.f : ex2a(s2 * 14.426950408889634f);
                sacc[nj][3] = (s3 < 0.f) ? 0.f : ex2a(s3 * 14.426950408889634f);
            }
            rlo += sacc[nj][0] + sacc[nj][1];
            rhi += sacc[nj][2] + sacc[nj][3];
        }

        // O += P V : A-fragment of P built from sacc via shfl relayout.
        // lane holds P cols {2tig,2tig+1}; needs cols {tig, tig+4}.
#pragma unroll
        for (int ks = 0; ks < 8; ks++) {
            float c0 = sacc[ks][0], c1 = sacc[ks][1];
            float c2 = sacc[ks][2], c3 = sacc[ks][3];
            float t0a = __shfl_sync(0xffffffffu, c0, src0);
            float t0b = __shfl_sync(0xffffffffu, c1, src0);
            float t1a = __shfl_sync(0xffffffffu, c2, src0);
            float t1b = __shfl_sync(0xffffffffu, c3, src0);
            float t2a = __shfl_sync(0xffffffffu, c0, src1);
            float t2b = __shfl_sync(0xffffffffu, c1, src1);
            float t3a = __shfl_sync(0xffffffffu, c2, src1);
            float t3b = __shfl_sync(0xffffffffu, c3, src1);
            uint32_t af[4];
            af[0] = f2tf(hi ? t0b : t0a);
            af[1] = f2tf(hi ? t1b : t1a);
            af[2] = f2tf(hi ? t2b : t2a);
            af[3] = f2tf(hi ? t3b : t3a);
            int kk = ks * 8;
#pragma unroll
            for (int nj = 0; nj < 8; nj++) {
                uint32_t bf[2];
                int vb = (kk + tig) * 72 + 8 * nj + g;
                bf[0] = sV[vb];
                bf[1] = sV[vb + 4 * 72];
                mma8(oacc[nj], af, bf);
            }
        }
    }

    rlo += __shfl_xor_sync(0xffffffffu, rlo, 1);
    rlo += __shfl_xor_sync(0xffffffffu, rlo, 2);
    rhi += __shfl_xor_sync(0xffffffffu, rhi, 1);
    rhi += __shfl_xor_sync(0xffffffffu, rhi, 2);
    float ilo = 1.f / rlo, ihi = 1.f / rhi;

    float* Ob = O + ((size_t)bh * N_ + row0 + wm + g) * D_;
#pragma unroll
    for (int nj = 0; nj < 8; nj++) {
        int c0 = 8 * nj + 2 * tig;
        float2 v0 = make_float2(oacc[nj][0] * ilo, oacc[nj][1] * ilo);
        float2 v1 = make_float2(oacc[nj][2] * ihi, oacc[nj][3] * ihi);
        *(float2*)(Ob + c0) = v0;
        *(float2*)(Ob + (size_t)8 * D_ + c0) = v1;
    }
}

// ---------------------------------------------------------------------------
__global__ void __launch_bounds__(256) normalize_kernel()
{
    int warp = (blockIdx.x * blockDim.x + threadIdx.x) >> 5;
    int lane = threadIdx.x & 31;
    if (warp >= BH_ * N_) return;
    float2 v = ((const float2*)(g_p1 + (size_t)warp * D_))[lane];
    float ss = v.x * v.x + v.y * v.y;
#pragma unroll
    for (int o = 16; o; o >>= 1) ss += __shfl_xor_sync(0xffffffffu, ss, o);
    float inv = 1.f / fmaxf(sqrtf(ss), 1e-12f);
    float2 o; o.x = v.x * inv; o.y = v.y * inv;
    ((float2*)(g_st + (size_t)warp * D_))[lane] = o;
}

// ---------------------------------------------------------------------------
extern "C" void kernel_launch(void* const* d_in, const int* in_sizes, int n_in,
                              void* d_out, int out_size)
{
    const float* x      = (const float*)d_in[0];
    const float* qkv_w  = (const float*)d_in[1];
    const float* qkv_b  = (const float*)d_in[2];
    const float* proj_w = (const float*)d_in[3];
    const float* proj_b = (const float*)d_in[4];
    float* out = (float*)d_out;

    cudaFuncSetAttribute(flash_mma<1>, cudaFuncAttributeMaxDynamicSharedMemorySize, FLASH_SMEM);
    cudaFuncSetAttribute(flash_mma<2>, cudaFuncAttributeMaxDynamicSharedMemorySize, FLASH_SMEM);

    // 1) QKV GEMM -> g_q/g_k/g_v (head layout)
    gemm_mma<0><<<dim3(18, 32), 256>>>(x, qkv_w, qkv_b, nullptr);
    // 2) stage-1 attention
    flash_mma<1><<<dim3(N_ / 128, BH_), 256, FLASH_SMEM>>>();
    // 3) first projection -> g_p1 (head layout)
    gemm_mma<1><<<dim3(6, 32), 256>>>(nullptr, proj_w, proj_b, nullptr);
    // 4) L2-normalize
    normalize_kernel<<<(BH_ * N_ * 32 + 255) / 256, 256>>>();
    // 5) stage-2 self-correlation attention
    flash_mma<2><<<dim3(N_ / 128, BH_), 256, FLASH_SMEM>>>();
    // 6) final projection -> d_out
    gemm_mma<2><<<dim3(6, 32), 256>>>(nullptr, proj_w, proj_b, out);
}

// round 11
// speedup vs baseline: 24.8541x; 1.5813x over previous
#include <cuda_runtime.h>
#include <cuda_fp16.h>
#include <math.h>
#include <stdint.h>

#define B_  2
#define N_  2048
#define C_  768
#define H_  12
#define D_  64
#define BH_ 24

// ---------------- scratch (device globals) ---------------------------------
__device__ float g_q [BH_*N_*D_];
__device__ float g_k [BH_*N_*D_];
__device__ float g_v [BH_*N_*D_];
__device__ float g_o1[BH_*N_*D_];
__device__ float g_p1[BH_*N_*D_];
__device__ float g_st[BH_*N_*D_];
__device__ float g_o2[BH_*N_*D_];

// ---------------- helpers ---------------------------------------------------
__device__ __forceinline__ uint32_t smem_u32(const void* p) {
    uint32_t a;
    asm("{ .reg .u64 t; cvta.to.shared.u64 t, %1; cvt.u32.u64 %0, t; }" : "=r"(a) : "l"(p));
    return a;
}
__device__ __forceinline__ float ex2a(float x) {
    float r;
    asm("ex2.approx.f32 %0, %1;" : "=f"(r) : "f"(x));
    return r;
}
__device__ __forceinline__ uint32_t pack2(float lo, float hi) {
    __half2 h = __floats2half2_rn(lo, hi);   // .x = lo (low half), .y = hi
    return *(uint32_t*)&h;
}
__device__ __forceinline__ uint2 cvt2(float4 v) {
    uint2 u;
    u.x = pack2(v.x, v.y);
    u.y = pack2(v.z, v.w);
    return u;
}

// D += A(16x16) * B(16x8), fp16 inputs, f32 accum
__device__ __forceinline__ void mma16(float* d, const uint32_t* a, const uint32_t* b) {
    asm volatile(
        "mma.sync.aligned.m16n8k16.row.col.f32.f16.f16.f32 "
        "{%0,%1,%2,%3}, {%4,%5,%6,%7}, {%8,%9}, {%0,%1,%2,%3};"
        : "+f"(d[0]), "+f"(d[1]), "+f"(d[2]), "+f"(d[3])
        : "r"(a[0]), "r"(a[1]), "r"(a[2]), "r"(a[3]), "r"(b[0]), "r"(b[1]));
}

// ---------------------------------------------------------------------------
// fp16 GEMM: Y[m,j] = sum_c A[m,c]*W[j,c] + bias[j].  BM=BN=128, BK=64.
// 8 warps 2x4, warp tile 64x32, 4 k16-slabs per BK.
// Row stride 36 words (72 halves): fragment loads conflict-free.
// MODE 0: A=x [B*N,C], W=[2304,768] -> scatter g_q/g_k/g_v
// MODE 1: A=gather(g_o1) [N*B,C]    -> scatter g_p1
// MODE 2: A=gather(g_o2) [N*B,C]    -> d_out [B,N,C]
// ---------------------------------------------------------------------------
template<int MODE>
__global__ void __launch_bounds__(256) gemm_mma(
    const float* __restrict__ Ain, const float* __restrict__ W,
    const float* __restrict__ bias, float* __restrict__ out)
{
    __shared__ uint32_t sA[128 * 36];
    __shared__ uint32_t sW[128 * 36];
    const int tid = threadIdx.x, w = tid >> 5, lane = tid & 31;
    const int g = lane >> 2, tig = lane & 3;
    const int bm = blockIdx.y * 128, bn = blockIdx.x * 128;
    const int wm = (w >> 2) * 64, wn = (w & 3) * 32;

    float acc[4][4][4];
#pragma unroll
    for (int mi = 0; mi < 4; mi++)
#pragma unroll
        for (int nj = 0; nj < 4; nj++)
#pragma unroll
            for (int c = 0; c < 4; c++) acc[mi][nj][c] = 0.f;

    for (int k0 = 0; k0 < C_; k0 += 64) {
        __syncthreads();
        // stage A + W tiles [128 x 64] as fp16
#pragma unroll
        for (int i = 0; i < 8; i++) {
            int idx = tid + i * 256;
            int r = idx >> 4, c4 = (idx & 15) * 4;
            float4 v;
            if (MODE == 0) {
                v = *(const float4*)(Ain + (size_t)(bm + r) * C_ + k0 + c4);
            } else {
                const float* src = (MODE == 1) ? g_o1 : g_o2;
                int m = bm + r, nn = m >> 1, bb = m & 1, h = k0 >> 6;
                v = *(const float4*)(src + (((size_t)(bb * H_ + h)) * N_ + nn) * D_ + c4);
            }
            *(uint2*)&sA[r * 36 + (idx & 15) * 2] = cvt2(v);
            float4 vw = *(const float4*)(W + (size_t)(bn + r) * C_ + k0 + c4);
            *(uint2*)&sW[r * 36 + (idx & 15) * 2] = cvt2(vw);
        }
        __syncthreads();
#pragma unroll
        for (int ks = 0; ks < 4; ks++) {
            int kk2 = ks * 8;
            uint32_t af[4][4], bf[4][2];
#pragma unroll
            for (int mi = 0; mi < 4; mi++) {
                int rb = (wm + 16 * mi + g) * 36 + kk2 + tig;
                af[mi][0] = sA[rb];
                af[mi][1] = sA[rb + 8 * 36];
                af[mi][2] = sA[rb + 4];
                af[mi][3] = sA[rb + 8 * 36 + 4];
            }
#pragma unroll
            for (int nj = 0; nj < 4; nj++) {
                int rb = (wn + 8 * nj + g) * 36 + kk2 + tig;
                bf[nj][0] = sW[rb];
                bf[nj][1] = sW[rb + 4];
            }
#pragma unroll
            for (int mi = 0; mi < 4; mi++)
#pragma unroll
                for (int nj = 0; nj < 4; nj++)
                    mma16(acc[mi][nj], af[mi], bf[nj]);
        }
    }

    // epilogue: c0/c1 at (row g), c2/c3 at (row g+8); cols 2*tig, 2*tig+1
#pragma unroll
    for (int mi = 0; mi < 4; mi++) {
        int r0 = bm + wm + 16 * mi + g;
        int r1 = r0 + 8;
#pragma unroll
        for (int nj = 0; nj < 4; nj++) {
            int c0 = bn + wn + 8 * nj + 2 * tig;
            float bx = bias[c0], by = bias[c0 + 1];
            float2 v0 = make_float2(acc[mi][nj][0] + bx, acc[mi][nj][1] + by);
            float2 v1 = make_float2(acc[mi][nj][2] + bx, acc[mi][nj][3] + by);
            if (MODE == 0) {
                int part = c0 / C_, jq = c0 - part * C_;
                int h = jq >> 6, d = jq & 63;
                float* base = (part == 0) ? g_q : ((part == 1) ? g_k : g_v);
                int bb0 = r0 >> 11, nn0 = r0 & (N_ - 1);
                int bb1 = r1 >> 11, nn1 = r1 & (N_ - 1);
                *(float2*)(base + (((size_t)(bb0 * H_ + h)) * N_ + nn0) * D_ + d) = v0;
                *(float2*)(base + (((size_t)(bb1 * H_ + h)) * N_ + nn1) * D_ + d) = v1;
            } else if (MODE == 1) {
                int h = c0 >> 6, d = c0 & 63;
                int nn0 = r0 >> 1, bb0 = r0 & 1;
                int nn1 = r1 >> 1, bb1 = r1 & 1;
                *(float2*)(g_p1 + (((size_t)(bb0 * H_ + h)) * N_ + nn0) * D_ + d) = v0;
                *(float2*)(g_p1 + (((size_t)(bb1 * H_ + h)) * N_ + nn1) * D_ + d) = v1;
            } else {
                int nn0 = r0 >> 1, bb0 = r0 & 1;
                int nn1 = r1 >> 1, bb1 = r1 & 1;
                *(float2*)(out + ((size_t)bb0 * N_ + nn0) * C_ + c0) = v0;
                *(float2*)(out + ((size_t)bb1 * N_ + nn1) * C_ + c0) = v1;
            }
        }
    }
}

// ---------------------------------------------------------------------------
// fp16 flash attention. 128 q rows/CTA, 8 warps x 16 rows, 64 keys/iter.
// S = QK^T via m16n8k16; P fed to O-mma directly from accumulator fragments
// (layouts coincide -> no shuffle/smem round-trip). V loaded row-major and
// fragmented with ldmatrix.x4.trans (stride 72 halves: conflict-free).
// STAGE 1: Q=g_q K=g_k scale .125 -> g_o1
// STAGE 2: Q=K=g_st scale 10, mask s<0 -> g_o2
// ---------------------------------------------------------------------------
template<int STAGE>
__global__ void __launch_bounds__(256, 2) flash_mma()
{
    __shared__ uint32_t sQh[128 * 36];
    __shared__ uint32_t sKh[64 * 36];
    __shared__ uint32_t sVh[64 * 36];

    const int tid = threadIdx.x, w = tid >> 5, lane = tid & 31;
    const int g = lane >> 2, tig = lane & 3;
    const int bh = blockIdx.y, row0 = blockIdx.x * 128;
    const int wm = w * 16;

    const float* Q  = (STAGE == 1) ? g_q : g_st;
    const float* Kp = (STAGE == 1) ? g_k : g_st;
    float*       O  = (STAGE == 1) ? g_o1 : g_o2;

    // stage Q [128 x 64] -> fp16
    const float* Qb = Q + ((size_t)bh * N_ + row0) * D_;
#pragma unroll
    for (int i = 0; i < 8; i++) {
        int idx = tid + i * 256;
        int r = idx >> 4, c4 = (idx & 15) * 4;
        *(uint2*)&sQh[r * 36 + (idx & 15) * 2] = cvt2(*(const float4*)(Qb + r * D_ + c4));
    }

    const float* KbB = Kp  + (size_t)bh * N_ * D_;
    const float* VbB = g_v + (size_t)bh * N_ * D_;

    // ldmatrix per-lane address components (V row-major, stride 36 words)
    const uint32_t svu = smem_u32(sVh);
    const int vrow = ((lane >> 3) & 1) * 8 + (lane & 7);
    const int vcolw = (lane >> 4) * 4;     // column offset in words (8 halves)

    float oacc[8][4];
#pragma unroll
    for (int nj = 0; nj < 8; nj++)
#pragma unroll
        for (int c = 0; c < 4; c++) oacc[nj][c] = 0.f;
    float rlo = 0.f, rhi = 0.f;

    for (int kt = 0; kt < N_; kt += 64) {
        // gmem loads before the barrier: latency overlaps barrier drain
        float4 kv[4], vv[4];
#pragma unroll
        for (int i = 0; i < 4; i++) {
            int idx = tid + i * 256;
            int r = idx >> 4, c4 = (idx & 15) * 4;
            kv[i] = *(const float4*)(KbB + (size_t)(kt + r) * D_ + c4);
            vv[i] = *(const float4*)(VbB + (size_t)(kt + r) * D_ + c4);
        }
        __syncthreads();   // prior iteration's readers done
#pragma unroll
        for (int i = 0; i < 4; i++) {
            int idx = tid + i * 256;
            int r = idx >> 4, wc = (idx & 15) * 2;
            *(uint2*)&sKh[r * 36 + wc] = cvt2(kv[i]);
            *(uint2*)&sVh[r * 36 + wc] = cvt2(vv[i]);
        }
        __syncthreads();   // staged tile visible (covers sQ on iter 0)

        // S = Q K^T  (warp's 16 rows x 64 keys), 4 k16-slabs
        float sacc[8][4];
#pragma unroll
        for (int nj = 0; nj < 8; nj++)
#pragma unroll
            for (int c = 0; c < 4; c++) sacc[nj][c] = 0.f;
#pragma unroll
        for (int ks = 0; ks < 4; ks++) {
            int kk2 = ks * 8;
            uint32_t af[4];
            int rb = (wm + g) * 36 + kk2 + tig;
            af[0] = sQh[rb];
            af[1] = sQh[rb + 8 * 36];
            af[2] = sQh[rb + 4];
            af[3] = sQh[rb + 8 * 36 + 4];
#pragma unroll
            for (int nj = 0; nj < 8; nj++) {
                uint32_t bf[2];
                int kb = (8 * nj + g) * 36 + kk2 + tig;
                bf[0] = sKh[kb];
                bf[1] = sKh[kb + 4];
                mma16(sacc[nj], af, bf);
            }
        }

        // softmax numerator in-place (scores bounded; no max subtraction)
#pragma unroll
        for (int nj = 0; nj < 8; nj++) {
            if (STAGE == 1) {
                sacc[nj][0] = ex2a(sacc[nj][0] * 0.18033688011112042f);
                sacc[nj][1] = ex2a(sacc[nj][1] * 0.18033688011112042f);
                sacc[nj][2] = ex2a(sacc[nj][2] * 0.18033688011112042f);
                sacc[nj][3] = ex2a(sacc[nj][3] * 0.18033688011112042f);
            } else {
                float s0 = sacc[nj][0], s1 = sacc[nj][1];
                float s2 = sacc[nj][2], s3 = sacc[nj][3];
                sacc[nj][0] = (s0 < 0.f) ? 0.f : ex2a(s0 * 14.426950408889634f);
                sacc[nj][1] = (s1 < 0.f) ? 0.f : ex2a(s1 * 14.426950408889634f);
                sacc[nj][2] = (s2 < 0.f) ? 0.f : ex2a(s2 * 14.426950408889634f);
                sacc[nj][3] = (s3 < 0.f) ? 0.f : ex2a(s3 * 14.426950408889634f);
            }
            rlo += sacc[nj][0] + sacc[nj][1];
            rhi += sacc[nj][2] + sacc[nj][3];
        }

        // O += P V : A-frags packed straight from sacc; B-frags via ldmatrix.trans
#pragma unroll
        for (int m = 0; m < 4; m++) {
            uint32_t ap[4];
            ap[0] = pack2(sacc[2*m    ][0], sacc[2*m    ][1]);
            ap[1] = pack2(sacc[2*m    ][2], sacc[2*m    ][3]);
            ap[2] = pack2(sacc[2*m + 1][0], sacc[2*m + 1][1]);
            ap[3] = pack2(sacc[2*m + 1][2], sacc[2*m + 1][3]);
#pragma unroll
            for (int dh = 0; dh < 4; dh++) {
                uint32_t vb[4];
                uint32_t addr = svu + (uint32_t)(((m * 16 + vrow) * 36 + dh * 8 + vcolw) * 4);
                asm volatile(
                    "ldmatrix.sync.aligned.m8n8.x4.trans.shared.b16 {%0,%1,%2,%3}, [%4];"
                    : "=r"(vb[0]), "=r"(vb[1]), "=r"(vb[2]), "=r"(vb[3]) : "r"(addr));
                mma16(oacc[2*dh],     ap, &vb[0]);
                mma16(oacc[2*dh + 1], ap, &vb[2]);
            }
        }
    }

    rlo += __shfl_xor_sync(0xffffffffu, rlo, 1);
    rlo += __shfl_xor_sync(0xffffffffu, rlo, 2);
    rhi += __shfl_xor_sync(0xffffffffu, rhi, 1);
    rhi += __shfl_xor_sync(0xffffffffu, rhi, 2);
    float ilo = 1.f / rlo, ihi = 1.f / rhi;

    float* Ob = O + ((size_t)bh * N_ + row0 + wm + g) * D_;
#pragma unroll
    for (int nj = 0; nj < 8; nj++) {
        int c0 = 8 * nj + 2 * tig;
        float2 v0 = make_float2(oacc[nj][0] * ilo, oacc[nj][1] * ilo);
        float2 v1 = make_float2(oacc[nj][2] * ihi, oacc[nj][3] * ihi);
        *(float2*)(Ob + c0) = v0;
        *(float2*)(Ob + (size_t)8 * D_ + c0) = v1;
    }
}

// ---------------------------------------------------------------------------
__global__ void __launch_bounds__(256) normalize_kernel()
{
    int warp = (blockIdx.x * blockDim.x + threadIdx.x) >> 5;
    int lane = threadIdx.x & 31;
    if (warp >= BH_ * N_) return;
    float2 v = ((const float2*)(g_p1 + (size_t)warp * D_))[lane];
    float ss = v.x * v.x + v.y * v.y;
#pragma unroll
    for (int o = 16; o; o >>= 1) ss += __shfl_xor_sync(0xffffffffu, ss, o);
    float inv = 1.f / fmaxf(sqrtf(ss), 1e-12f);
    float2 o; o.x = v.x * inv; o.y = v.y * inv;
    ((float2*)(g_st + (size_t)warp * D_))[lane] = o;
}

// ---------------------------------------------------------------------------
extern "C" void kernel_launch(void* const* d_in, const int* in_sizes, int n_in,
                              void* d_out, int out_size)
{
    const float* x      = (const float*)d_in[0];
    const float* qkv_w  = (const float*)d_in[1];
    const float* qkv_b  = (const float*)d_in[2];
    const float* proj_w = (const float*)d_in[3];
    const float* proj_b = (const float*)d_in[4];
    float* out = (float*)d_out;

    // 1) QKV GEMM -> g_q/g_k/g_v (head layout)
    gemm_mma<0><<<dim3(18, 32), 256>>>(x, qkv_w, qkv_b, nullptr);
    // 2) stage-1 attention
    flash_mma<1><<<dim3(N_ / 128, BH_), 256>>>();
    // 3) first projection -> g_p1 (head layout)
    gemm_mma<1><<<dim3(6, 32), 256>>>(nullptr, proj_w, proj_b, nullptr);
    // 4) L2-normalize
    normalize_kernel<<<(BH_ * N_ * 32 + 255) / 256, 256>>>();
    // 5) stage-2 self-correlation attention
    flash_mma<2><<<dim3(N_ / 128, BH_), 256>>>();
    // 6) final projection -> d_out
    gemm_mma<2><<<dim3(6, 32), 256>>>(nullptr, proj_w, proj_b, out);
}

// round 12
// speedup vs baseline: 30.4848x; 1.2265x over previous
#include <cuda_runtime.h>
#include <cuda_fp16.h>
#include <math.h>
#include <stdint.h>

#define B_  2
#define N_  2048
#define C_  768
#define H_  12
#define D_  64
#define BH_ 24

// ---------------- scratch (device globals) ---------------------------------
__device__ __half g_x16 [B_*N_*C_];
__device__ __half g_qw16[3*C_*C_];
__device__ __half g_pw16[C_*C_];
__device__ __half g_q [BH_*N_*D_];
__device__ __half g_k [BH_*N_*D_];
__device__ __half g_v [BH_*N_*D_];
__device__ __half g_o1[BH_*N_*D_];
__device__ float  g_p1[BH_*N_*D_];
__device__ __half g_st[BH_*N_*D_];
__device__ __half g_o2[BH_*N_*D_];

// ---------------- helpers ---------------------------------------------------
__device__ __forceinline__ uint32_t smem_u32(const void* p) {
    uint32_t a;
    asm("{ .reg .u64 t; cvta.to.shared.u64 t, %1; cvt.u32.u64 %0, t; }" : "=r"(a) : "l"(p));
    return a;
}
__device__ __forceinline__ float ex2a(float x) {
    float r;
    asm("ex2.approx.f32 %0, %1;" : "=f"(r) : "f"(x));
    return r;
}
__device__ __forceinline__ uint32_t pack2(float lo, float hi) {
    __half2 h = __floats2half2_rn(lo, hi);
    return *(uint32_t*)&h;
}
__device__ __forceinline__ void cpa16(uint32_t dst, const void* src) {
    asm volatile("cp.async.cg.shared.global [%0], [%1], 16;" :: "r"(dst), "l"(src));
}
#define CPA_COMMIT() asm volatile("cp.async.commit_group;" ::: "memory")
#define CPA_WAIT0()  asm volatile("cp.async.wait_group 0;" ::: "memory")

// D += A(16x16) * B(16x8), fp16 inputs, f32 accum
__device__ __forceinline__ void mma16(float* d, const uint32_t* a, const uint32_t* b) {
    asm volatile(
        "mma.sync.aligned.m16n8k16.row.col.f32.f16.f16.f32 "
        "{%0,%1,%2,%3}, {%4,%5,%6,%7}, {%8,%9}, {%0,%1,%2,%3};"
        : "+f"(d[0]), "+f"(d[1]), "+f"(d[2]), "+f"(d[3])
        : "r"(a[0]), "r"(a[1]), "r"(a[2]), "r"(a[3]), "r"(b[0]), "r"(b[1]));
}
__device__ __forceinline__ void ldm4(uint32_t* r, uint32_t addr) {
    asm volatile("ldmatrix.sync.aligned.m8n8.x4.shared.b16 {%0,%1,%2,%3}, [%4];"
                 : "=r"(r[0]), "=r"(r[1]), "=r"(r[2]), "=r"(r[3]) : "r"(addr));
}
__device__ __forceinline__ void ldm4t(uint32_t* r, uint32_t addr) {
    asm volatile("ldmatrix.sync.aligned.m8n8.x4.trans.shared.b16 {%0,%1,%2,%3}, [%4];"
                 : "=r"(r[0]), "=r"(r[1]), "=r"(r[2]), "=r"(r[3]) : "r"(addr));
}

// ---------------------------------------------------------------------------
// fp32 -> fp16 conversion (pre-pass for x / qkv_w / proj_w)
// ---------------------------------------------------------------------------
__global__ void __launch_bounds__(256) f2h_kernel(const float* __restrict__ s,
                                                 __half* __restrict__ d, int n2)
{
    int i = blockIdx.x * blockDim.x + threadIdx.x;
    if (i < n2) {
        float2 v = ((const float2*)s)[i];
        ((__half2*)d)[i] = __floats2half2_rn(v.x, v.y);
    }
}

// ---------------------------------------------------------------------------
// fp16 GEMM, all-fp16 inputs, cp.async double-buffered.  BM=BN=128, BK=64,
// 8 warps 2x4, warp tile 64x32.  Tile rows: 72 halves (144B) stride.
// MODE 0: A=g_x16 [B*N,C], W=g_qw16  -> scatter g_q/g_k/g_v (fp16)
// MODE 1: A=g_o1 [BH,N,D] gathered,  W=g_pw16 -> g_p1 (fp32)
// MODE 2: A=g_o2 gathered,           W=g_pw16 -> d_out (fp32)
// ---------------------------------------------------------------------------
#define GEMM_SMEM (4 * 128 * 72 * 2)   // A0,A1,W0,W1 tiles

template<int MODE>
__global__ void __launch_bounds__(256, 2) gemm_mma(
    const float* __restrict__ bias, float* __restrict__ out)
{
    extern __shared__ __half smem[];
    const uint32_t sb = smem_u32(smem);
    const uint32_t A0 = sb, A1 = sb + 128*144, W0 = sb + 2*128*144, W1 = sb + 3*128*144;

    const int tid = threadIdx.x, w = tid >> 5, lane = tid & 31;
    const int g = lane >> 2, tig = lane & 3;
    const int bm = blockIdx.y * 128, bn = blockIdx.x * 128;
    const int wm = (w >> 2) * 64, wn = (w & 3) * 32;
    const int lrow = lane & 15, lc16 = (lane >> 4) * 16;

    const __half* A16 = (MODE == 0) ? g_x16 : ((MODE == 1) ? g_o1 : g_o2);
    const __half* W16 = (MODE == 0) ? g_qw16 : g_pw16;

    // staging chunk coords: 4 chunks per thread per tile
    const int pr = tid >> 1;           // rows pr, pr+... (128 rows, 8 chunks each)
    // chunk id c = tid + i*256 : r = c>>3, cc = c&7
    auto issue_tile = [&](uint32_t abuf, uint32_t wbuf, int k0) {
#pragma unroll
        for (int i = 0; i < 4; i++) {
            int c = tid + i * 256;
            int r = c >> 3, cc = c & 7;
            uint32_t doff = (uint32_t)(r * 144 + cc * 16);
            const __half* asrc;
            if (MODE == 0) {
                asrc = A16 + (size_t)(bm + r) * C_ + k0 + cc * 8;
            } else {
                int m = bm + r, nn = m >> 1, bb = m & 1, h = k0 >> 6;
                asrc = A16 + (((size_t)(bb * H_ + h)) * N_ + nn) * D_ + cc * 8;
            }
            cpa16(abuf + doff, asrc);
            cpa16(wbuf + doff, W16 + (size_t)(bn + r) * C_ + k0 + cc * 8);
        }
        CPA_COMMIT();
    };
    (void)pr;

    float acc[4][4][4];
#pragma unroll
    for (int mi = 0; mi < 4; mi++)
#pragma unroll
        for (int nj = 0; nj < 4; nj++)
#pragma unroll
            for (int c = 0; c < 4; c++) acc[mi][nj][c] = 0.f;

    issue_tile(A0, W0, 0);

    for (int k0 = 0; k0 < C_; k0 += 64) {
        const int buf = (k0 >> 6) & 1;
        const uint32_t ab = buf ? A1 : A0, wb = buf ? W1 : W0;
        CPA_WAIT0();
        __syncthreads();
        if (k0 + 64 < C_)
            issue_tile(buf ? A0 : A1, buf ? W0 : W1, k0 + 64);

#pragma unroll
        for (int ks = 0; ks < 4; ks++) {
            uint32_t af[4][4], bf[2][4];
#pragma unroll
            for (int mi = 0; mi < 4; mi++)
                ldm4(af[mi], ab + (uint32_t)((wm + 16*mi + lrow) * 144 + ks * 32 + lc16));
#pragma unroll
            for (int p = 0; p < 2; p++)
                ldm4(bf[p], wb + (uint32_t)((wn + 16*p + lrow) * 144 + ks * 32 + lc16));
#pragma unroll
            for (int mi = 0; mi < 4; mi++)
#pragma unroll
                for (int nj = 0; nj < 4; nj++) {
                    uint32_t bb2[2] = { bf[nj >> 1][(nj & 1)], bf[nj >> 1][(nj & 1) + 2] };
                    mma16(acc[mi][nj], af[mi], bb2);
                }
        }
    }

    // epilogue
#pragma unroll
    for (int mi = 0; mi < 4; mi++) {
        int r0 = bm + wm + 16 * mi + g;
        int r1 = r0 + 8;
#pragma unroll
        for (int nj = 0; nj < 4; nj++) {
            int c0 = bn + wn + 8 * nj + 2 * tig;
            float bx = bias[c0], by = bias[c0 + 1];
            float a0 = acc[mi][nj][0] + bx, a1 = acc[mi][nj][1] + by;
            float a2 = acc[mi][nj][2] + bx, a3 = acc[mi][nj][3] + by;
            if (MODE == 0) {
                int part = c0 / C_, jq = c0 - part * C_;
                int h = jq >> 6, d = jq & 63;
                __half* base = (part == 0) ? g_q : ((part == 1) ? g_k : g_v);
                int bb0 = r0 >> 11, nn0 = r0 & (N_ - 1);
                int bb1 = r1 >> 11, nn1 = r1 & (N_ - 1);
                *(__half2*)(base + (((size_t)(bb0*H_ + h))*N_ + nn0)*D_ + d) = __floats2half2_rn(a0, a1);
                *(__half2*)(base + (((size_t)(bb1*H_ + h))*N_ + nn1)*D_ + d) = __floats2half2_rn(a2, a3);
            } else if (MODE == 1) {
                int h = c0 >> 6, d = c0 & 63;
                int nn0 = r0 >> 1, bb0 = r0 & 1;
                int nn1 = r1 >> 1, bb1 = r1 & 1;
                *(float2*)(g_p1 + (((size_t)(bb0*H_ + h))*N_ + nn0)*D_ + d) = make_float2(a0, a1);
                *(float2*)(g_p1 + (((size_t)(bb1*H_ + h))*N_ + nn1)*D_ + d) = make_float2(a2, a3);
            } else {
                int nn0 = r0 >> 1, bb0 = r0 & 1;
                int nn1 = r1 >> 1, bb1 = r1 & 1;
                *(float2*)(out + ((size_t)bb0*N_ + nn0)*C_ + c0) = make_float2(a0, a1);
                *(float2*)(out + ((size_t)bb1*N_ + nn1)*C_ + c0) = make_float2(a2, a3);
            }
        }
    }
}

// ---------------------------------------------------------------------------
// fp16 flash attention, cp.async double-buffered K/V, Q fragments hoisted.
// 128 q rows/CTA, 8 warps x 16 rows, 64 keys/iter, one barrier per iter.
// STAGE 1: Q=g_q K=g_k scale .125 -> g_o1 (fp16)
// STAGE 2: Q=K=g_st scale 10, mask s<0 -> g_o2 (fp16)
// ---------------------------------------------------------------------------
#define FLASH_SMEM ((128*72 + 4*64*72) * 2)

template<int STAGE>
__global__ void __launch_bounds__(256, 2) flash_mma()
{
    extern __shared__ __half smem[];
    const uint32_t sb = smem_u32(smem);
    const uint32_t SQ = sb;
    const uint32_t K0 = sb + 128*144, K1 = K0 + 64*144;
    const uint32_t V0 = K1 + 64*144,  V1 = V0 + 64*144;

    const int tid = threadIdx.x, w = tid >> 5, lane = tid & 31;
    const int g = lane >> 2, tig = lane & 3;
    const int bh = blockIdx.y, row0 = blockIdx.x * 128;
    const int wm = w * 16;
    const int lrow = lane & 15, lc16 = (lane >> 4) * 16;
    const int vrow = ((lane >> 3) & 1) * 8 + (lane & 7), vc16 = (lane >> 4) * 16;

    const __half* Q  = (STAGE == 1) ? g_q : g_st;
    const __half* Kp = (STAGE == 1) ? g_k : g_st;
    __half*       O  = (STAGE == 1) ? g_o1 : g_o2;

    const __half* Qg = Q  + ((size_t)bh * N_ + row0) * D_;
    const __half* Kg = Kp + (size_t)bh * N_ * D_;
    const __half* Vg = g_v + (size_t)bh * N_ * D_;

    auto issue_kv = [&](uint32_t kbuf, uint32_t vbuf, int kt) {
#pragma unroll
        for (int i = 0; i < 2; i++) {
            int c = tid + i * 256;
            int r = c >> 3, cc = c & 7;
            uint32_t doff = (uint32_t)(r * 144 + cc * 16);
            cpa16(kbuf + doff, Kg + (size_t)(kt + r) * D_ + cc * 8);
            cpa16(vbuf + doff, Vg + (size_t)(kt + r) * D_ + cc * 8);
        }
        CPA_COMMIT();
    };

    // prologue: Q + first K/V tile
#pragma unroll
    for (int i = 0; i < 4; i++) {
        int c = tid + i * 256;
        int r = c >> 3, cc = c & 7;
        cpa16(SQ + (uint32_t)(r * 144 + cc * 16), Qg + (size_t)r * D_ + cc * 8);
    }
    issue_kv(K0, V0, 0);   // commits Q chunks too (same group)
    CPA_WAIT0();
    __syncthreads();

    // hoist Q fragments (16 regs); sQ never read again
    uint32_t qf[4][4];
#pragma unroll
    for (int ks = 0; ks < 4; ks++)
        ldm4(qf[ks], SQ + (uint32_t)((wm + lrow) * 144 + ks * 32 + lc16));

    float oacc[8][4];
#pragma unroll
    for (int nj = 0; nj < 8; nj++)
#pragma unroll
        for (int c = 0; c < 4; c++) oacc[nj][c] = 0.f;
    float rlo = 0.f, rhi = 0.f;

    for (int kt = 0; kt < N_; kt += 64) {
        const int buf = (kt >> 6) & 1;
        const uint32_t kb = buf ? K1 : K0, vb = buf ? V1 : V0;
        if (kt > 0) { CPA_WAIT0(); __syncthreads(); }
        if (kt + 64 < N_)
            issue_kv(buf ? K0 : K1, buf ? V0 : V1, kt + 64);

        // S = Q K^T
        float sacc[8][4];
#pragma unroll
        for (int nj = 0; nj < 8; nj++)
#pragma unroll
            for (int c = 0; c < 4; c++) sacc[nj][c] = 0.f;
#pragma unroll
        for (int ks = 0; ks < 4; ks++) {
#pragma unroll
            for (int p = 0; p < 4; p++) {
                uint32_t km[4];
                ldm4(km, kb + (uint32_t)((16*p + lrow) * 144 + ks * 32 + lc16));
                uint32_t b0[2] = { km[0], km[2] };
                uint32_t b1[2] = { km[1], km[3] };
                mma16(sacc[2*p],     qf[ks], b0);
                mma16(sacc[2*p + 1], qf[ks], b1);
            }
        }

        // softmax numerator (scores bounded; no max subtraction)
#pragma unroll
        for (int nj = 0; nj < 8; nj++) {
            if (STAGE == 1) {
                sacc[nj][0] = ex2a(sacc[nj][0] * 0.18033688011112042f);
                sacc[nj][1] = ex2a(sacc[nj][1] * 0.18033688011112042f);
                sacc[nj][2] = ex2a(sacc[nj][2] * 0.18033688011112042f);
                sacc[nj][3] = ex2a(sacc[nj][3] * 0.18033688011112042f);
            } else {
                float s0 = sacc[nj][0], s1 = sacc[nj][1];
                float s2 = sacc[nj][2], s3 = sacc[nj][3];
                sacc[nj][0] = (s0 < 0.f) ? 0.f : ex2a(s0 * 14.426950408889634f);
                sacc[nj][1] = (s1 < 0.f) ? 0.f : ex2a(s1 * 14.426950408889634f);
                sacc[nj][2] = (s2 < 0.f) ? 0.f : ex2a(s2 * 14.426950408889634f);
                sacc[nj][3] = (s3 < 0.f) ? 0.f : ex2a(s3 * 14.426950408889634f);
            }
            rlo += sacc[nj][0] + sacc[nj][1];
            rhi += sacc[nj][2] + sacc[nj][3];
        }

        // O += P V : P packed straight from accumulators
#pragma unroll
        for (int m = 0; m < 4; m++) {
            uint32_t ap[4];
            ap[0] = pack2(sacc[2*m    ][0], sacc[2*m    ][1]);
            ap[1] = pack2(sacc[2*m    ][2], sacc[2*m    ][3]);
            ap[2] = pack2(sacc[2*m + 1][0], sacc[2*m + 1][1]);
            ap[3] = pack2(sacc[2*m + 1][2], sacc[2*m + 1][3]);
#pragma unroll
            for (int dh = 0; dh < 4; dh++) {
                uint32_t vm[4];
                ldm4t(vm, vb + (uint32_t)((m * 16 + vrow) * 144 + dh * 32 + vc16));
                mma16(oacc[2*dh],     ap, &vm[0]);
                mma16(oacc[2*dh + 1], ap, &vm[2]);
            }
        }
    }

    rlo += __shfl_xor_sync(0xffffffffu, rlo, 1);
    rlo += __shfl_xor_sync(0xffffffffu, rlo, 2);
    rhi += __shfl_xor_sync(0xffffffffu, rhi, 1);
    rhi += __shfl_xor_sync(0xffffffffu, rhi, 2);
    float ilo = 1.f / rlo, ihi = 1.f / rhi;

    __half* Ob = O + ((size_t)bh * N_ + row0 + wm + g) * D_;
#pragma unroll
    for (int nj = 0; nj < 8; nj++) {
        int c0 = 8 * nj + 2 * tig;
        *(__half2*)(Ob + c0) = __floats2half2_rn(oacc[nj][0] * ilo, oacc[nj][1] * ilo);
        *(__half2*)(Ob + (size_t)8 * D_ + c0) = __floats2half2_rn(oacc[nj][2] * ihi, oacc[nj][3] * ihi);
    }
}

// ---------------------------------------------------------------------------
// Row-normalize g_p1 (fp32) -> g_st (fp16): one warp per row.
// ---------------------------------------------------------------------------
__global__ void __launch_bounds__(256) normalize_kernel()
{
    int warp = (blockIdx.x * blockDim.x + threadIdx.x) >> 5;
    int lane = threadIdx.x & 31;
    if (warp >= BH_ * N_) return;
    float2 v = ((const float2*)(g_p1 + (size_t)warp * D_))[lane];
    float ss = v.x * v.x + v.y * v.y;
#pragma unroll
    for (int o = 16; o; o >>= 1) ss += __shfl_xor_sync(0xffffffffu, ss, o);
    float inv = 1.f / fmaxf(sqrtf(ss), 1e-12f);
    ((__half2*)(g_st + (size_t)warp * D_))[lane] = __floats2half2_rn(v.x * inv, v.y * inv);
}

// ---------------------------------------------------------------------------
extern "C" void kernel_launch(void* const* d_in, const int* in_sizes, int n_in,
                              void* d_out, int out_size)
{
    const float* x      = (const float*)d_in[0];
    const float* qkv_w  = (const float*)d_in[1];
    const float* qkv_b  = (const float*)d_in[2];
    const float* proj_w = (const float*)d_in[3];
    const float* proj_b = (const float*)d_in[4];
    float* out = (float*)d_out;

    static int attr_done = 0;
    if (!attr_done) {
        cudaFuncSetAttribute(gemm_mma<0>, cudaFuncAttributeMaxDynamicSharedMemorySize, GEMM_SMEM);
        cudaFuncSetAttribute(gemm_mma<1>, cudaFuncAttributeMaxDynamicSharedMemorySize, GEMM_SMEM);
        cudaFuncSetAttribute(gemm_mma<2>, cudaFuncAttributeMaxDynamicSharedMemorySize, GEMM_SMEM);
        cudaFuncSetAttribute(flash_mma<1>, cudaFuncAttributeMaxDynamicSharedMemorySize, FLASH_SMEM);
        cudaFuncSetAttribute(flash_mma<2>, cudaFuncAttributeMaxDynamicSharedMemorySize, FLASH_SMEM);
        attr_done = 1;
    }

    __half* dx16; __half* dqw16; __half* dpw16;
    cudaGetSymbolAddress((void**)&dx16,  g_x16);
    cudaGetSymbolAddress((void**)&dqw16, g_qw16);
    cudaGetSymbolAddress((void**)&dpw16, g_pw16);

    // 0) fp32 -> fp16 pre-pass
    f2h_kernel<<<(B_*N_*C_/2 + 255)/256, 256>>>(x,      dx16,  B_*N_*C_/2);
    f2h_kernel<<<(3*C_*C_/2 + 255)/256, 256>>>(qkv_w,  dqw16, 3*C_*C_/2);
    f2h_kernel<<<(C_*C_/2   + 255)/256, 256>>>(proj_w, dpw16, C_*C_/2);

    // 1) QKV GEMM -> g_q/g_k/g_v (fp16, head layout)
    gemm_mma<0><<<dim3(18, 32), 256, GEMM_SMEM>>>(qkv_b, nullptr);
    // 2) stage-1 attention
    flash_mma<1><<<dim3(N_ / 128, BH_), 256, FLASH_SMEM>>>();
    // 3) first projection -> g_p1 (fp32, head layout)
    gemm_mma<1><<<dim3(6, 32), 256, GEMM_SMEM>>>(proj_b, nullptr);
    // 4) L2-normalize -> g_st (fp16)
    normalize_kernel<<<(BH_ * N_ * 32 + 255) / 256, 256>>>();
    // 5) stage-2 self-correlation attention
    flash_mma<2><<<dim3(N_ / 128, BH_), 256, FLASH_SMEM>>>();
    // 6) final projection -> d_out (fp32)
    gemm_mma<2><<<dim3(6, 32), 256, GEMM_SMEM>>>(proj_b, out);
}

// round 14
// speedup vs baseline: 30.5780x; 1.0031x over previous
#include <cuda_runtime.h>
#include <cuda_fp16.h>
#include <math.h>
#include <stdint.h>

#define B_  2
#define N_  2048
#define C_  768
#define H_  12
#define D_  64
#define BH_ 24

// ---------------- scratch (device globals) ---------------------------------
__device__ __half g_x16 [B_*N_*C_];
__device__ __half g_qw16[3*C_*C_];
__device__ __half g_pw16[C_*C_];
__device__ __half g_q [BH_*N_*D_];
__device__ __half g_k [BH_*N_*D_];
__device__ __half g_v [BH_*N_*D_];
__device__ __half g_o1[BH_*N_*D_];
__device__ __half g_st[BH_*N_*D_];
__device__ __half g_o2[BH_*N_*D_];

// ---------------- helpers ---------------------------------------------------
__device__ __forceinline__ uint32_t smem_u32(const void* p) {
    uint32_t a;
    asm("{ .reg .u64 t; cvta.to.shared.u64 t, %1; cvt.u32.u64 %0, t; }" : "=r"(a) : "l"(p));
    return a;
}
__device__ __forceinline__ float ex2a(float x) {
    float r;
    asm("ex2.approx.f32 %0, %1;" : "=f"(r) : "f"(x));
    return r;
}
__device__ __forceinline__ uint32_t pack2(float lo, float hi) {
    __half2 h = __floats2half2_rn(lo, hi);
    return *(uint32_t*)&h;
}
__device__ __forceinline__ void cpa16(uint32_t dst, const void* src) {
    asm volatile("cp.async.cg.shared.global [%0], [%1], 16;" :: "r"(dst), "l"(src));
}
#define CPA_COMMIT() asm volatile("cp.async.commit_group;" ::: "memory")
#define CPA_WAIT0()  asm volatile("cp.async.wait_group 0;" ::: "memory")

// D += A(16x16) * B(16x8), fp16 inputs, f32 accum
__device__ __forceinline__ void mma16(float* d, const uint32_t* a, const uint32_t* b) {
    asm volatile(
        "mma.sync.aligned.m16n8k16.row.col.f32.f16.f16.f32 "
        "{%0,%1,%2,%3}, {%4,%5,%6,%7}, {%8,%9}, {%0,%1,%2,%3};"
        : "+f"(d[0]), "+f"(d[1]), "+f"(d[2]), "+f"(d[3])
        : "r"(a[0]), "r"(a[1]), "r"(a[2]), "r"(a[3]), "r"(b[0]), "r"(b[1]));
}
__device__ __forceinline__ void ldm4(uint32_t* r, uint32_t addr) {
    asm volatile("ldmatrix.sync.aligned.m8n8.x4.shared.b16 {%0,%1,%2,%3}, [%4];"
                 : "=r"(r[0]), "=r"(r[1]), "=r"(r[2]), "=r"(r[3]) : "r"(addr));
}
__device__ __forceinline__ void ldm4t(uint32_t* r, uint32_t addr) {
    asm volatile("ldmatrix.sync.aligned.m8n8.x4.trans.shared.b16 {%0,%1,%2,%3}, [%4];"
                 : "=r"(r[0]), "=r"(r[1]), "=r"(r[2]), "=r"(r[3]) : "r"(addr));
}

// ---------------------------------------------------------------------------
// fp32 -> fp16 conversion (pre-pass for x / qkv_w / proj_w)
// ---------------------------------------------------------------------------
__global__ void __launch_bounds__(256) f2h_kernel(const float* __restrict__ s,
                                                 __half* __restrict__ d, int n2)
{
    int i = blockIdx.x * blockDim.x + threadIdx.x;
    if (i < n2) {
        float2 v = ((const float2*)s)[i];
        ((__half2*)d)[i] = __floats2half2_rn(v.x, v.y);
    }
}

// ---------------------------------------------------------------------------
// fp16 GEMM, cp.async double-buffered.  BM=BN=128, BK=64, 8 warps 2x4,
// warp tile 64x32.  Tile row stride 72 halves (144B).
// MODE 0: A=g_x16 [B*N,C], W=g_qw16  -> scatter g_q/g_k/g_v (fp16)
// MODE 1: A=g_o1 gathered, W=g_pw16  -> FUSED L2-normalize -> g_st (fp16)
// MODE 2: A=g_o2 gathered, W=g_pw16  -> d_out (fp32)
// ---------------------------------------------------------------------------
#define GEMM_SMEM (4 * 128 * 72 * 2)   // A0,A1,W0,W1 tiles

template<int MODE>
__global__ void __launch_bounds__(256, 2) gemm_mma(
    const float* __restrict__ bias, float* __restrict__ out)
{
    extern __shared__ __half smem[];
    const uint32_t sb = smem_u32(smem);
    const uint32_t A0 = sb, A1 = sb + 128*144, W0 = sb + 2*128*144, W1 = sb + 3*128*144;

    const int tid = threadIdx.x, w = tid >> 5, lane = tid & 31;
    const int g = lane >> 2, tig = lane & 3;
    const int bm = blockIdx.y * 128, bn = blockIdx.x * 128;
    const int wm = (w >> 2) * 64, wn = (w & 3) * 32;
    const int lrow = lane & 15, lc16 = (lane >> 4) * 16;

    const __half* A16 = (MODE == 0) ? g_x16 : ((MODE == 1) ? g_o1 : g_o2);
    const __half* W16 = (MODE == 0) ? g_qw16 : g_pw16;

    auto issue_tile = [&](uint32_t abuf, uint32_t wbuf, int k0) {
#pragma unroll
        for (int i = 0; i < 4; i++) {
            int c = tid + i * 256;
            int r = c >> 3, cc = c & 7;
            uint32_t doff = (uint32_t)(r * 144 + cc * 16);
            const __half* asrc;
            if (MODE == 0) {
                asrc = A16 + (size_t)(bm + r) * C_ + k0 + cc * 8;
            } else {
                int m = bm + r, nn = m >> 1, bb = m & 1, h = k0 >> 6;
                asrc = A16 + (((size_t)(bb * H_ + h)) * N_ + nn) * D_ + cc * 8;
            }
            cpa16(abuf + doff, asrc);
            cpa16(wbuf + doff, W16 + (size_t)(bn + r) * C_ + k0 + cc * 8);
        }
        CPA_COMMIT();
    };

    float acc[4][4][4];
#pragma unroll
    for (int mi = 0; mi < 4; mi++)
#pragma unroll
        for (int nj = 0; nj < 4; nj++)
#pragma unroll
            for (int c = 0; c < 4; c++) acc[mi][nj][c] = 0.f;

    issue_tile(A0, W0, 0);

    for (int k0 = 0; k0 < C_; k0 += 64) {
        const int buf = (k0 >> 6) & 1;
        const uint32_t ab = buf ? A1 : A0, wb = buf ? W1 : W0;
        CPA_WAIT0();
        __syncthreads();
        if (k0 + 64 < C_)
            issue_tile(buf ? A0 : A1, buf ? W0 : W1, k0 + 64);

#pragma unroll
        for (int ks = 0; ks < 4; ks++) {
            uint32_t af[4][4], bf[2][4];
#pragma unroll
            for (int mi = 0; mi < 4; mi++)
                ldm4(af[mi], ab + (uint32_t)((wm + 16*mi + lrow) * 144 + ks * 32 + lc16));
#pragma unroll
            for (int p = 0; p < 2; p++)
                ldm4(bf[p], wb + (uint32_t)((wn + 16*p + lrow) * 144 + ks * 32 + lc16));
#pragma unroll
            for (int mi = 0; mi < 4; mi++)
#pragma unroll
                for (int nj = 0; nj < 4; nj++) {
                    uint32_t bb2[2] = { bf[nj >> 1][(nj & 1)], bf[nj >> 1][(nj & 1) + 2] };
                    mma16(acc[mi][nj], af[mi], bb2);
                }
        }
    }

    if (MODE == 1) {
        // fused L2-normalize epilogue: CTA tile = 128 rows x 128 cols = 2 heads.
        // Warp-column index wc = wn>>5 (0..3); head 0 <- partial slots {0,1},
        // head 1 <- slots {2,3}; this warp's head-pair base = (wn>>6)*2.
        float* P = (float*)smem;          // [128][4] row partials (reuse smem)
        const int wc = wn >> 5;
        const int hbase = (wn >> 6) * 2;
        __syncthreads();                  // tiles fully consumed
#pragma unroll
        for (int mi = 0; mi < 4; mi++) {
            float s0 = 0.f, s1 = 0.f;
#pragma unroll
            for (int nj = 0; nj < 4; nj++) {
                int c0 = bn + wn + 8 * nj + 2 * tig;
                float bx = bias[c0], by = bias[c0 + 1];
                acc[mi][nj][0] += bx; acc[mi][nj][1] += by;
                acc[mi][nj][2] += bx; acc[mi][nj][3] += by;
                s0 += acc[mi][nj][0]*acc[mi][nj][0] + acc[mi][nj][1]*acc[mi][nj][1];
                s1 += acc[mi][nj][2]*acc[mi][nj][2] + acc[mi][nj][3]*acc[mi][nj][3];
            }
            s0 += __shfl_xor_sync(0xffffffffu, s0, 1);
            s0 += __shfl_xor_sync(0xffffffffu, s0, 2);
            s1 += __shfl_xor_sync(0xffffffffu, s1, 1);
            s1 += __shfl_xor_sync(0xffffffffu, s1, 2);
            if (tig == 0) {
                P[(wm + 16*mi + g) * 4 + wc]     = s0;
                P[(wm + 16*mi + g + 8) * 4 + wc] = s1;
            }
        }
        __syncthreads();
#pragma unroll
        for (int mi = 0; mi < 4; mi++) {
            int lr0 = wm + 16*mi + g, lr1 = lr0 + 8;
            float inv0 = 1.f / fmaxf(sqrtf(P[lr0*4 + hbase] + P[lr0*4 + hbase + 1]), 1e-12f);
            float inv1 = 1.f / fmaxf(sqrtf(P[lr1*4 + hbase] + P[lr1*4 + hbase + 1]), 1e-12f);
            int r0 = bm + lr0, r1 = bm + lr1;
#pragma unroll
            for (int nj = 0; nj < 4; nj++) {
                int c0 = bn + wn + 8 * nj + 2 * tig;
                int h = c0 >> 6, d = c0 & 63;
                int nn0 = r0 >> 1, bb0 = r0 & 1;
                int nn1 = r1 >> 1, bb1 = r1 & 1;
                *(__half2*)(g_st + (((size_t)(bb0*H_ + h))*N_ + nn0)*D_ + d) =
                    __floats2half2_rn(acc[mi][nj][0]*inv0, acc[mi][nj][1]*inv0);
                *(__half2*)(g_st + (((size_t)(bb1*H_ + h))*N_ + nn1)*D_ + d) =
                    __floats2half2_rn(acc[mi][nj][2]*inv1, acc[mi][nj][3]*inv1);
            }
        }
        return;
    }

    // epilogue MODE 0 / 2
#pragma unroll
    for (int mi = 0; mi < 4; mi++) {
        int r0 = bm + wm + 16 * mi + g;
        int r1 = r0 + 8;
#pragma unroll
        for (int nj = 0; nj < 4; nj++) {
            int c0 = bn + wn + 8 * nj + 2 * tig;
            float bx = bias[c0], by = bias[c0 + 1];
            float a0 = acc[mi][nj][0] + bx, a1 = acc[mi][nj][1] + by;
            float a2 = acc[mi][nj][2] + bx, a3 = acc[mi][nj][3] + by;
            if (MODE == 0) {
                int part = c0 / C_, jq = c0 - part * C_;
                int h = jq >> 6, d = jq & 63;
                __half* base = (part == 0) ? g_q : ((part == 1) ? g_k : g_v);
                int bb0 = r0 >> 11, nn0 = r0 & (N_ - 1);
                int bb1 = r1 >> 11, nn1 = r1 & (N_ - 1);
                *(__half2*)(base + (((size_t)(bb0*H_ + h))*N_ + nn0)*D_ + d) = __floats2half2_rn(a0, a1);
                *(__half2*)(base + (((size_t)(bb1*H_ + h))*N_ + nn1)*D_ + d) = __floats2half2_rn(a2, a3);
            } else {
                int nn0 = r0 >> 1, bb0 = r0 & 1;
                int nn1 = r1 >> 1, bb1 = r1 & 1;
                *(float2*)(out + ((size_t)bb0*N_ + nn0)*C_ + c0) = make_float2(a0, a1);
                *(float2*)(out + ((size_t)bb1*N_ + nn1)*C_ + c0) = make_float2(a2, a3);
            }
        }
    }
}

// ---------------------------------------------------------------------------
// fp16 flash attention: 128 threads (4 warps) x 64 q-rows per CTA, 64 keys
// per iter, cp.async double-buffered K/V, Q fragments hoisted.  Static smem
// (45KB) -> ~4 CTAs/SM for cross-CTA phase staggering.
// STAGE 1: Q=g_q K=g_k scale .125 -> g_o1 (fp16)
// STAGE 2: Q=K=g_st scale 10, mask s<0 -> g_o2 (fp16)
// ---------------------------------------------------------------------------
template<int STAGE>
__global__ void __launch_bounds__(128, 4) flash_mma()
{
    __shared__ __half sbuf[5 * 64 * 72];
    const uint32_t sb = smem_u32(sbuf);
    const uint32_t SQ = sb;
    const uint32_t K0 = sb + 64*144, K1 = K0 + 64*144;
    const uint32_t V0 = K1 + 64*144, V1 = V0 + 64*144;

    const int tid = threadIdx.x, w = tid >> 5, lane = tid & 31;
    const int g = lane >> 2, tig = lane & 3;
    const int bh = blockIdx.y, row0 = blockIdx.x * 64;
    const int wm = w * 16;
    const int lrow = lane & 15, lc16 = (lane >> 4) * 16;
    const int vrow = ((lane >> 3) & 1) * 8 + (lane & 7), vc16 = (lane >> 4) * 16;

    const __half* Q  = (STAGE == 1) ? g_q : g_st;
    const __half* Kp = (STAGE == 1) ? g_k : g_st;
    __half*       O  = (STAGE == 1) ? g_o1 : g_o2;

    const __half* Qg = Q  + ((size_t)bh * N_ + row0) * D_;
    const __half* Kg = Kp + (size_t)bh * N_ * D_;
    const __half* Vg = g_v + (size_t)bh * N_ * D_;

    auto issue_kv = [&](uint32_t kbuf, uint32_t vbuf, int kt) {
#pragma unroll
        for (int i = 0; i < 4; i++) {
            int c = tid + i * 128;
            int r = c >> 3, cc = c & 7;
            uint32_t doff = (uint32_t)(r * 144 + cc * 16);
            cpa16(kbuf + doff, Kg + (size_t)(kt + r) * D_ + cc * 8);
            cpa16(vbuf + doff, Vg + (size_t)(kt + r) * D_ + cc * 8);
        }
        CPA_COMMIT();
    };

    // prologue: Q + first K/V tile
#pragma unroll
    for (int i = 0; i < 4; i++) {
        int c = tid + i * 128;
        int r = c >> 3, cc = c & 7;
        cpa16(SQ + (uint32_t)(r * 144 + cc * 16), Qg + (size_t)r * D_ + cc * 8);
    }
    issue_kv(K0, V0, 0);   // commits Q chunks too (same group)
    CPA_WAIT0();
    __syncthreads();

    // hoist Q fragments (16 regs); sQ never read again
    uint32_t qf[4][4];
#pragma unroll
    for (int ks = 0; ks < 4; ks++)
        ldm4(qf[ks], SQ + (uint32_t)((wm + lrow) * 144 + ks * 32 + lc16));

    float oacc[8][4];
#pragma unroll
    for (int nj = 0; nj < 8; nj++)
#pragma unroll
        for (int c = 0; c < 4; c++) oacc[nj][c] = 0.f;
    float rlo = 0.f, rhi = 0.f;

    for (int kt = 0; kt < N_; kt += 64) {
        const int buf = (kt >> 6) & 1;
        const uint32_t kb = buf ? K1 : K0, vb = buf ? V1 : V0;
        if (kt > 0) { CPA_WAIT0(); __syncthreads(); }
        if (kt + 64 < N_)
            issue_kv(buf ? K0 : K1, buf ? V0 : V1, kt + 64);

        // S = Q K^T
        float sacc[8][4];
#pragma unroll
        for (int nj = 0; nj < 8; nj++)
#pragma unroll
            for (int c = 0; c < 4; c++) sacc[nj][c] = 0.f;
#pragma unroll
        for (int ks = 0; ks < 4; ks++) {
#pragma unroll
            for (int p = 0; p < 4; p++) {
                uint32_t km[4];
                ldm4(km, kb + (uint32_t)((16*p + lrow) * 144 + ks * 32 + lc16));
                uint32_t b0[2] = { km[0], km[2] };
                uint32_t b1[2] = { km[1], km[3] };
                mma16(sacc[2*p],     qf[ks], b0);
                mma16(sacc[2*p + 1], qf[ks], b1);
            }
        }

        // softmax numerator (scores bounded; no max subtraction)
#pragma unroll
        for (int nj = 0; nj < 8; nj++) {
            if (STAGE == 1) {
                sacc[nj][0] = ex2a(sacc[nj][0] * 0.18033688011112042f);
                sacc[nj][1] = ex2a(sacc[nj][1] * 0.18033688011112042f);
                sacc[nj][2] = ex2a(sacc[nj][2] * 0.18033688011112042f);
                sacc[nj][3] = ex2a(sacc[nj][3] * 0.18033688011112042f);
            } else {
                float s0 = sacc[nj][0], s1 = sacc[nj][1];
                float s2 = sacc[nj][2], s3 = sacc[nj][3];
                sacc[nj][0] = (s0 < 0.f) ? 0.f : ex2a(s0 * 14.426950408889634f);
                sacc[nj][1] = (s1 < 0.f) ? 0.f : ex2a(s1 * 14.426950408889634f);
                sacc[nj][2] = (s2 < 0.f) ? 0.f : ex2a(s2 * 14.426950408889634f);
                sacc[nj][3] = (s3 < 0.f) ? 0.f : ex2a(s3 * 14.426950408889634f);
            }
            rlo += sacc[nj][0] + sacc[nj][1];
            rhi += sacc[nj][2] + sacc[nj][3];
        }

        // O += P V : P packed straight from accumulators
#pragma unroll
        for (int m = 0; m < 4; m++) {
            uint32_t ap[4];
            ap[0] = pack2(sacc[2*m    ][0], sacc[2*m    ][1]);
            ap[1] = pack2(sacc[2*m    ][2], sacc[2*m    ][3]);
            ap[2] = pack2(sacc[2*m + 1][0], sacc[2*m + 1][1]);
            ap[3] = pack2(sacc[2*m + 1][2], sacc[2*m + 1][3]);
#pragma unroll
            for (int dh = 0; dh < 4; dh++) {
                uint32_t vm[4];
                ldm4t(vm, vb + (uint32_t)((m * 16 + vrow) * 144 + dh * 32 + vc16));
                mma16(oacc[2*dh],     ap, &vm[0]);
                mma16(oacc[2*dh + 1], ap, &vm[2]);
            }
        }
    }

    rlo += __shfl_xor_sync(0xffffffffu, rlo, 1);
    rlo += __shfl_xor_sync(0xffffffffu, rlo, 2);
    rhi += __shfl_xor_sync(0xffffffffu, rhi, 1);
    rhi += __shfl_xor_sync(0xffffffffu, rhi, 2);
    float ilo = 1.f / rlo, ihi = 1.f / rhi;

    __half* Ob = O + ((size_t)bh * N_ + row0 + wm + g) * D_;
#pragma unroll
    for (int nj = 0; nj < 8; nj++) {
        int c0 = 8 * nj + 2 * tig;
        *(__half2*)(Ob + c0) = __floats2half2_rn(oacc[nj][0] * ilo, oacc[nj][1] * ilo);
        *(__half2*)(Ob + (size_t)8 * D_ + c0) = __floats2half2_rn(oacc[nj][2] * ihi, oacc[nj][3] * ihi);
    }
}

// ---------------------------------------------------------------------------
extern "C" void kernel_launch(void* const* d_in, const int* in_sizes, int n_in,
                              void* d_out, int out_size)
{
    const float* x      = (const float*)d_in[0];
    const float* qkv_w  = (const float*)d_in[1];
    const float* qkv_b  = (const float*)d_in[2];
    const float* proj_w = (const float*)d_in[3];
    const float* proj_b = (const float*)d_in[4];
    float* out = (float*)d_out;

    cudaFuncSetAttribute(gemm_mma<0>, cudaFuncAttributeMaxDynamicSharedMemorySize, GEMM_SMEM);
    cudaFuncSetAttribute(gemm_mma<1>, cudaFuncAttributeMaxDynamicSharedMemorySize, GEMM_SMEM);
    cudaFuncSetAttribute(gemm_mma<2>, cudaFuncAttributeMaxDynamicSharedMemorySize, GEMM_SMEM);

    __half* dx16; __half* dqw16; __half* dpw16;
    cudaGetSymbolAddress((void**)&dx16,  g_x16);
    cudaGetSymbolAddress((void**)&dqw16, g_qw16);
    cudaGetSymbolAddress((void**)&dpw16, g_pw16);

    // 0) fp32 -> fp16 pre-pass
    f2h_kernel<<<(B_*N_*C_/2 + 255)/256, 256>>>(x,      dx16,  B_*N_*C_/2);
    f2h_kernel<<<(3*C_*C_/2 + 255)/256, 256>>>(qkv_w,  dqw16, 3*C_*C_/2);
    f2h_kernel<<<(C_*C_/2   + 255)/256, 256>>>(proj_w, dpw16, C_*C_/2);

    // 1) QKV GEMM -> g_q/g_k/g_v (fp16, head layout)
    gemm_mma<0><<<dim3(18, 32), 256, GEMM_SMEM>>>(qkv_b, nullptr);
    // 2) stage-1 attention
    flash_mma<1><<<dim3(N_ / 64, BH_), 128>>>();
    // 3) first projection + FUSED L2-normalize -> g_st (fp16)
    gemm_mma<1><<<dim3(6, 32), 256, GEMM_SMEM>>>(proj_b, nullptr);
    // 4) stage-2 self-correlation attention
    flash_mma<2><<<dim3(N_ / 64, BH_), 128>>>();
    // 5) final projection -> d_out (fp32)
    gemm_mma<2><<<dim3(6, 32), 256, GEMM_SMEM>>>(proj_b, out);
}